// round 1
// baseline (speedup 1.0000x reference)
#include <cuda_runtime.h>
#include <cuda_fp16.h>
#include <cuda_bf16.h>
#include <mma.h>
#include <stdint.h>

using namespace nvcuda;

// Problem constants
#define BATCH 4
#define SEQ   2048
#define HID   1024
#define NFREQ 513          // H/2 + 1
#define KD    1056         // 2*NFREQ padded to multiple of 32
#define ROWS  (BATCH * SEQ)      // 8192

// Scratch (static __device__ — no allocations allowed)
__device__ __half g_qf[(size_t)ROWS * KD];        // 17.3 MB  [row][kd] cos|sin features of Q
__device__ __half g_kf[(size_t)ROWS * KD];        // 17.3 MB  same for K
__device__ __half g_wh[(size_t)ROWS * SEQ];       // 32 MB    fp16 softmax weights
__device__ __half g_vh[(size_t)ROWS * HID];       // 16 MB    fp16 V

// ---------------------------------------------------------------------------
// Kernel 1: per-row FFT-1024 (radix-2, shared mem) -> phase features
// cos(phase)=re/|z|, sin(phase)=im/|z|  (no atan2/cos/sin needed)
// grid = 2*ROWS blocks (first half Q, second half K), 256 threads
// ---------------------------------------------------------------------------
__global__ void fft_phase_kernel(const float* __restrict__ Q,
                                 const float* __restrict__ K)
{
    __shared__ float sre[1024];
    __shared__ float sim[1024];
    __shared__ float twc[512];
    __shared__ float tws[512];

    const int t = threadIdx.x;                 // 256 threads
    const bool isK = blockIdx.x >= ROWS;
    const int row = blockIdx.x & (ROWS - 1);
    const float* src = (isK ? K : Q) + (size_t)row * HID;
    __half* dst = (isK ? g_kf : g_qf) + (size_t)row * KD;

    // twiddle table: exp(-2*pi*i*m/1024), m = 0..511
    for (int m = t; m < 512; m += 256) {
        float ang = -6.283185307179586f * (float)m * (1.0f / 1024.0f);
        float s, c;
        sincosf(ang, &s, &c);
        twc[m] = c;
        tws[m] = s;
    }

    // bit-reversed load, imag = 0
    for (int i = t; i < 1024; i += 256) {
        int r = __brev((unsigned)i) >> 22;
        sre[r] = src[i];
        sim[r] = 0.0f;
    }
    __syncthreads();

    // 10 radix-2 stages
#pragma unroll
    for (int s = 1; s <= 10; s++) {
        const int half = 1 << (s - 1);
        const int tsh  = 10 - s;               // twiddle index = k << tsh
#pragma unroll 2
        for (int b = t; b < 512; b += 256) {
            const int k   = b & (half - 1);
            const int grp = b >> (s - 1);
            const int pos = (grp << s) + k;
            const float c = twc[k << tsh];
            const float sn = tws[k << tsh];
            const float ur = sre[pos],        ui = sim[pos];
            const float vr = sre[pos + half], vi = sim[pos + half];
            const float tr = vr * c - vi * sn;
            const float ti = vr * sn + vi * c;
            sre[pos]        = ur + tr;
            sim[pos]        = ui + ti;
            sre[pos + half] = ur - tr;
            sim[pos + half] = ui - ti;
        }
        __syncthreads();
    }

    // normalized features: [0..512] = cos(phase), [513..1025] = sin(phase), pad 0
    for (int k = t; k < NFREQ; k += 256) {
        const float re = sre[k], im = sim[k];
        const float mag2 = re * re + im * im;
        float cc, ss;
        if (mag2 > 0.0f) {
            const float inv = rsqrtf(mag2);
            cc = re * inv;
            ss = im * inv;
        } else {               // atan2(0,0) = 0
            cc = 1.0f;
            ss = 0.0f;
        }
        dst[k]         = __float2half(cc);
        dst[NFREQ + k] = __float2half(ss);
    }
    for (int k = 2 * NFREQ + t; k < KD; k += 256)
        dst[k] = __float2half(0.0f);
}

// ---------------------------------------------------------------------------
// Kernel 2: V fp32 -> fp16
// ---------------------------------------------------------------------------
__global__ void vconv_kernel(const float* __restrict__ V)
{
    const size_t base = ((size_t)blockIdx.x * 256 + threadIdx.x) * 4;
    const float4 f = *(const float4*)(V + base);
    __half h[4];
    h[0] = __float2half(f.x);
    h[1] = __float2half(f.y);
    h[2] = __float2half(f.z);
    h[3] = __float2half(f.w);
    *(uint2*)(g_vh + base) = *(uint2*)h;
}

// ---------------------------------------------------------------------------
// Kernel 3: GEMM1 — scores[b,i,j] = dot(QF[b,i,:], KF[b,j,:]) / 513 + 1
// A row-major [SEQ,KD], B = KF (K-contiguous => wmma col_major)
// Block 128x128x32, 8 warps (2x4), warp tile 64x32
// ---------------------------------------------------------------------------
__global__ void gemm1_kernel(float* __restrict__ Wout)
{
    constexpr int BM = 128, BN = 128, BK = 32, PAD = 8;
    __shared__ __half sa[BM][BK + PAD];
    __shared__ __half sb[BN][BK + PAD];

    const int b  = blockIdx.z;
    const int m0 = blockIdx.x * BM;
    const int n0 = blockIdx.y * BN;
    const __half* A  = g_qf + (size_t)b * SEQ * KD;
    const __half* Bm = g_kf + (size_t)b * SEQ * KD;

    const int tid  = threadIdx.x;              // 256
    const int warp = tid >> 5;
    const int wm = warp >> 2;                  // 0..1
    const int wn = warp & 3;                   // 0..3

    wmma::fragment<wmma::accumulator, 16, 16, 16, float> fc[4][2];
#pragma unroll
    for (int i = 0; i < 4; i++)
#pragma unroll
        for (int j = 0; j < 2; j++)
            wmma::fill_fragment(fc[i][j], 0.0f);

    for (int kt = 0; kt < KD / BK; kt++) {
        const int k0 = kt * BK;
#pragma unroll
        for (int r = 0; r < 2; r++) {
            const int idx = tid + r * 256;     // 0..511
            const int row = idx >> 2;          // 0..127
            const int c4  = idx & 3;           // 0..3 (8 halves each)
            *(uint4*)&sa[row][c4 * 8] =
                *(const uint4*)(A  + (size_t)(m0 + row) * KD + k0 + c4 * 8);
            *(uint4*)&sb[row][c4 * 8] =
                *(const uint4*)(Bm + (size_t)(n0 + row) * KD + k0 + c4 * 8);
        }
        __syncthreads();

#pragma unroll
        for (int kk = 0; kk < BK; kk += 16) {
            wmma::fragment<wmma::matrix_a, 16, 16, 16, __half, wmma::row_major> fa[4];
            wmma::fragment<wmma::matrix_b, 16, 16, 16, __half, wmma::col_major> fb[2];
#pragma unroll
            for (int i = 0; i < 4; i++)
                wmma::load_matrix_sync(fa[i], &sa[wm * 64 + i * 16][kk], BK + PAD);
#pragma unroll
            for (int j = 0; j < 2; j++)
                wmma::load_matrix_sync(fb[j], &sb[wn * 32 + j * 16][kk], BK + PAD);
#pragma unroll
            for (int i = 0; i < 4; i++)
#pragma unroll
                for (int j = 0; j < 2; j++)
                    wmma::mma_sync(fc[i][j], fa[i], fb[j], fc[i][j]);
        }
        __syncthreads();
    }

    const float invF = 1.0f / 513.0f;
    float* W = Wout + (size_t)b * SEQ * SEQ;
#pragma unroll
    for (int i = 0; i < 4; i++)
#pragma unroll
        for (int j = 0; j < 2; j++) {
#pragma unroll
            for (int e = 0; e < fc[i][j].num_elements; e++)
                fc[i][j].x[e] = fc[i][j].x[e] * invF + 1.0f;
            wmma::store_matrix_sync(
                W + (size_t)(m0 + wm * 64 + i * 16) * SEQ + n0 + wn * 32 + j * 16,
                fc[i][j], SEQ, wmma::mem_row_major);
        }
}

// ---------------------------------------------------------------------------
// Kernel 4: row softmax over 2048 fp32 (in place) + fp16 copy into g_wh
// one block per row, 256 threads x 8 elems
// ---------------------------------------------------------------------------
__global__ void softmax_kernel(float* __restrict__ W)
{
    __shared__ float smax[8];
    __shared__ float ssum[8];
    const size_t row = blockIdx.x;
    float* p  = W    + row * SEQ;
    __half* ph = g_wh + row * SEQ;
    const int t = threadIdx.x;

    float v[8];
    float m = -1e30f;
#pragma unroll
    for (int i = 0; i < 8; i++) {
        v[i] = p[t + 256 * i];
        m = fmaxf(m, v[i]);
    }
#pragma unroll
    for (int o = 16; o; o >>= 1) m = fmaxf(m, __shfl_xor_sync(0xffffffffu, m, o));
    if ((t & 31) == 0) smax[t >> 5] = m;
    __syncthreads();
    m = smax[0];
#pragma unroll
    for (int i = 1; i < 8; i++) m = fmaxf(m, smax[i]);

    float s = 0.0f;
#pragma unroll
    for (int i = 0; i < 8; i++) {
        v[i] = __expf(v[i] - m);
        s += v[i];
    }
#pragma unroll
    for (int o = 16; o; o >>= 1) s += __shfl_xor_sync(0xffffffffu, s, o);
    if ((t & 31) == 0) ssum[t >> 5] = s;
    __syncthreads();
    s = ssum[0];
#pragma unroll
    for (int i = 1; i < 8; i++) s += ssum[i];
    const float inv = 1.0f / s;

#pragma unroll
    for (int i = 0; i < 8; i++) {
        const float w = v[i] * inv;
        p[t + 256 * i]  = w;
        ph[t + 256 * i] = __float2half(w);
    }
}

// ---------------------------------------------------------------------------
// Kernel 5: GEMM2 — out[b,i,h] = sum_j W16[b,i,j] * V16[b,j,h]
// A row-major [SEQ,SEQ], B row-major [SEQ,HID]
// ---------------------------------------------------------------------------
__global__ void gemm2_kernel(float* __restrict__ Out)
{
    constexpr int BM = 128, BN = 128, BK = 32, PAD = 8;
    __shared__ __half sa[BM][BK + PAD];
    __shared__ __half sb[BK][BN + PAD];

    const int b  = blockIdx.z;
    const int m0 = blockIdx.x * BM;            // over SEQ
    const int n0 = blockIdx.y * BN;            // over HID
    const __half* A  = g_wh + (size_t)b * SEQ * SEQ;
    const __half* Bv = g_vh + (size_t)b * SEQ * HID;

    const int tid  = threadIdx.x;
    const int warp = tid >> 5;
    const int wm = warp >> 2;
    const int wn = warp & 3;

    wmma::fragment<wmma::accumulator, 16, 16, 16, float> fc[4][2];
#pragma unroll
    for (int i = 0; i < 4; i++)
#pragma unroll
        for (int j = 0; j < 2; j++)
            wmma::fill_fragment(fc[i][j], 0.0f);

    for (int kt = 0; kt < SEQ / BK; kt++) {
        const int k0 = kt * BK;
#pragma unroll
        for (int r = 0; r < 2; r++) {
            const int idx = tid + r * 256;     // 0..511
            const int rowA = idx >> 2;         // 0..127
            const int c4   = idx & 3;
            *(uint4*)&sa[rowA][c4 * 8] =
                *(const uint4*)(A + (size_t)(m0 + rowA) * SEQ + k0 + c4 * 8);
            const int rowB = idx >> 4;         // 0..31
            const int c16  = idx & 15;
            *(uint4*)&sb[rowB][c16 * 8] =
                *(const uint4*)(Bv + (size_t)(k0 + rowB) * HID + n0 + c16 * 8);
        }
        __syncthreads();

#pragma unroll
        for (int kk = 0; kk < BK; kk += 16) {
            wmma::fragment<wmma::matrix_a, 16, 16, 16, __half, wmma::row_major> fa[4];
            wmma::fragment<wmma::matrix_b, 16, 16, 16, __half, wmma::row_major> fb[2];
#pragma unroll
            for (int i = 0; i < 4; i++)
                wmma::load_matrix_sync(fa[i], &sa[wm * 64 + i * 16][kk], BK + PAD);
#pragma unroll
            for (int j = 0; j < 2; j++)
                wmma::load_matrix_sync(fb[j], &sb[kk][wn * 32 + j * 16], BN + PAD);
#pragma unroll
            for (int i = 0; i < 4; i++)
#pragma unroll
                for (int j = 0; j < 2; j++)
                    wmma::mma_sync(fc[i][j], fa[i], fb[j], fc[i][j]);
        }
        __syncthreads();
    }

    float* O = Out + (size_t)b * SEQ * HID;
#pragma unroll
    for (int i = 0; i < 4; i++)
#pragma unroll
        for (int j = 0; j < 2; j++)
            wmma::store_matrix_sync(
                O + (size_t)(m0 + wm * 64 + i * 16) * HID + n0 + wn * 32 + j * 16,
                fc[i][j], HID, wmma::mem_row_major);
}

// ---------------------------------------------------------------------------
// Launch: out = [output (B*S*H fp32) | weights (B*S*S fp32)]
// ---------------------------------------------------------------------------
extern "C" void kernel_launch(void* const* d_in, const int* in_sizes, int n_in,
                              void* d_out, int out_size)
{
    const float* Q = (const float*)d_in[0];
    const float* K = (const float*)d_in[1];
    const float* V = (const float*)d_in[2];
    float* out     = (float*)d_out;
    float* weights = out + (size_t)BATCH * SEQ * HID;   // scores/weights region

    // 1) phase features for Q and K
    fft_phase_kernel<<<2 * ROWS, 256>>>(Q, K);

    // 2) V -> fp16
    vconv_kernel<<<(BATCH * SEQ * HID) / (256 * 4), 256>>>(V);

    // 3) scores = QF . KF^T / 513 + 1  (fp32, into weights region)
    {
        dim3 grid(SEQ / 128, SEQ / 128, BATCH);
        gemm1_kernel<<<grid, 256>>>(weights);
    }

    // 4) softmax rows in place (+ fp16 copy)
    softmax_kernel<<<ROWS, 256>>>(weights);

    // 5) output = weights @ V
    {
        dim3 grid(SEQ / 128, HID / 128, BATCH);
        gemm2_kernel<<<grid, 256>>>(out);
    }
}

// round 3
// speedup vs baseline: 1.0588x; 1.0588x over previous
#include <cuda_runtime.h>
#include <cuda_fp16.h>
#include <stdint.h>

// Problem constants
#define BATCH 4
#define SEQ   2048
#define HID   1024
#define NFREQ 513           // H/2 + 1
#define KD    1088          // 2*NFREQ (=1026) padded to multiple of 32
#define ROWS  (BATCH * SEQ) // 8192

// Scratch (static __device__ — no allocations allowed)
__device__ __align__(256) __half g_qf[(size_t)ROWS * KD];         // Q phase features
__device__ __align__(256) __half g_kf[(size_t)ROWS * KD];         // K phase features
__device__ __align__(256) __half g_wh[(size_t)ROWS * SEQ];        // fp16 softmax weights
__device__ __align__(256) __half g_vt[(size_t)BATCH * HID * SEQ]; // V^T [b][h][j] fp16

// ===========================================================================
// PTX helpers
// ===========================================================================
__device__ __forceinline__ uint32_t smem_u32(const void* p) {
    uint32_t a;
    asm("{ .reg .u64 t; cvta.to.shared.u64 t, %1; cvt.u32.u64 %0, t; }"
        : "=r"(a) : "l"(p));
    return a;
}
__device__ __forceinline__ void cp16(uint32_t dst, const void* src) {
    asm volatile("cp.async.cg.shared.global [%0], [%1], 16;" :: "r"(dst), "l"(src));
}
__device__ __forceinline__ void cp_commit() {
    asm volatile("cp.async.commit_group;" ::: "memory");
}
template <int N> __device__ __forceinline__ void cp_wait() {
    asm volatile("cp.async.wait_group %0;" :: "n"(N) : "memory");
}

#define LDSM4(r, a)                                                          \
    asm volatile("ldmatrix.sync.aligned.m8n8.x4.shared.b16 {%0,%1,%2,%3}, [%4];" \
                 : "=r"((r)[0]), "=r"((r)[1]), "=r"((r)[2]), "=r"((r)[3])    \
                 : "r"(a))

#define MMA16816(d, a0, a1, a2, a3, b0, b1)                                  \
    asm volatile(                                                            \
        "mma.sync.aligned.m16n8k16.row.col.f32.f16.f16.f32 "                 \
        "{%0,%1,%2,%3}, {%4,%5,%6,%7}, {%8,%9}, {%0,%1,%2,%3};"              \
        : "+f"((d)[0]), "+f"((d)[1]), "+f"((d)[2]), "+f"((d)[3])             \
        : "r"(a0), "r"(a1), "r"(a2), "r"(a3), "r"(b0), "r"(b1))

// ===========================================================================
// Kernel 1: per-row FFT-1024 -> normalized phase features (cos|sin), fp16
// ===========================================================================
__global__ void fft_phase_kernel(const float* __restrict__ Q,
                                 const float* __restrict__ K)
{
    __shared__ float sre[1024];
    __shared__ float sim[1024];
    __shared__ float twc[512];
    __shared__ float tws[512];

    const int t = threadIdx.x;                 // 256 threads
    const bool isK = blockIdx.x >= ROWS;
    const int row = blockIdx.x & (ROWS - 1);
    const float* src = (isK ? K : Q) + (size_t)row * HID;
    __half* dst = (isK ? g_kf : g_qf) + (size_t)row * KD;

    for (int m = t; m < 512; m += 256) {
        float ang = -6.283185307179586f * (float)m * (1.0f / 1024.0f);
        float s, c;
        sincosf(ang, &s, &c);
        twc[m] = c;
        tws[m] = s;
    }
    for (int i = t; i < 1024; i += 256) {
        int r = __brev((unsigned)i) >> 22;
        sre[r] = src[i];
        sim[r] = 0.0f;
    }
    __syncthreads();

#pragma unroll
    for (int s = 1; s <= 10; s++) {
        const int half = 1 << (s - 1);
        const int tsh  = 10 - s;
#pragma unroll 2
        for (int b = t; b < 512; b += 256) {
            const int k   = b & (half - 1);
            const int grp = b >> (s - 1);
            const int pos = (grp << s) + k;
            const float c  = twc[k << tsh];
            const float sn = tws[k << tsh];
            const float ur = sre[pos],        ui = sim[pos];
            const float vr = sre[pos + half], vi = sim[pos + half];
            const float tr = vr * c - vi * sn;
            const float ti = vr * sn + vi * c;
            sre[pos]        = ur + tr;
            sim[pos]        = ui + ti;
            sre[pos + half] = ur - tr;
            sim[pos + half] = ui - ti;
        }
        __syncthreads();
    }

    for (int k = t; k < NFREQ; k += 256) {
        const float re = sre[k], im = sim[k];
        const float mag2 = re * re + im * im;
        float cc, ss;
        if (mag2 > 0.0f) {
            const float inv = rsqrtf(mag2);
            cc = re * inv;
            ss = im * inv;
        } else {
            cc = 1.0f;
            ss = 0.0f;
        }
        dst[k]         = __float2half(cc);
        dst[NFREQ + k] = __float2half(ss);
    }
    for (int k = 2 * NFREQ + t; k < KD; k += 256)
        dst[k] = __float2half(0.0f);
}

// ===========================================================================
// Kernel 2: V [b][j][h] fp32 -> g_vt [b][h][j] fp16 (32x32 smem transpose)
// ===========================================================================
__global__ void vtrans_kernel(const float* __restrict__ V)
{
    __shared__ float s[32][33];
    const int b  = blockIdx.z;
    const int h0 = blockIdx.x * 32;
    const int j0 = blockIdx.y * 32;
    const int tx = threadIdx.x, ty = threadIdx.y;   // 32 x 8

    const float* src = V + ((size_t)b * SEQ + j0) * HID + h0;
#pragma unroll
    for (int r = 0; r < 32; r += 8)
        s[ty + r][tx] = src[(size_t)(ty + r) * HID + tx];
    __syncthreads();

    __half* dst = g_vt + ((size_t)b * HID + h0) * SEQ + j0;
#pragma unroll
    for (int r = 0; r < 32; r += 8)
        dst[(size_t)(ty + r) * SEQ + tx] = __float2half(s[tx][ty + r]);
}

// ===========================================================================
// Kernel 3/5: pipelined HMMA (mma.sync m16n8k16) NT GEMM, 128x128x32 tiles.
// MODE 0: scores = QF.KF^T/513 + 1.  MODE 1: out = W.V  (V pre-transposed).
// A [m][k], B [n][k], both k-contiguous fp16. 3-stage cp.async ring.
// Smem rows padded to 80B -> conflict-free ldmatrix (banks 20r mod 32).
// ===========================================================================
#define LDS_H    40                         // halves per smem row (32 + 8 pad)
#define TILE_B   (128 * LDS_H * 2)          // 10240 bytes per operand tile
#define STG_B    (2 * TILE_B)               // 20480 per stage
#define NSTAGE   3
#define GEMM_SMEM (NSTAGE * STG_B)          // 61440

template <int MODE>
__global__ void __launch_bounds__(256, 2) gemm_hmma(float* __restrict__ Dbase)
{
    constexpr int  KT  = (MODE == 0) ? KD : SEQ;
    constexpr int  LDA = (MODE == 0) ? KD : SEQ;
    constexpr int  LDB = (MODE == 0) ? KD : SEQ;
    constexpr long long ABS = (MODE == 0) ? (long long)SEQ * KD : (long long)SEQ * SEQ;
    constexpr long long BBS = (MODE == 0) ? (long long)SEQ * KD : (long long)HID * SEQ;
    constexpr int  LDD = (MODE == 0) ? SEQ : HID;
    constexpr long long DBS = (long long)SEQ * LDD;
    constexpr int  NC  = KT / 32;

    extern __shared__ __align__(256) char smem[];
    const uint32_t sb = smem_u32(smem);

    const int tid  = threadIdx.x;
    const int warp = tid >> 5;
    const int lane = tid & 31;
    const int wm   = warp & 3;              // 4 warps along M (32 rows each)
    const int wn   = warp >> 2;             // 2 warps along N (64 cols each)
    const int m0 = blockIdx.x * 128;
    const int n0 = blockIdx.y * 128;
    const int bz = blockIdx.z;

    const __half* A = ((MODE == 0) ? g_qf : g_wh) + (long long)bz * ABS + (long long)m0 * LDA;
    const __half* B = ((MODE == 0) ? g_kf : g_vt) + (long long)bz * BBS + (long long)n0 * LDB;

    // per-lane ldmatrix base offsets (within a tile)
    const int lr = lane & 15;               // row within 16
    const int lc = lane >> 4;               // 8-col group

    auto load_chunk = [&](int st, int kc) {
        const uint32_t abase = sb + st * STG_B;
        const uint32_t bbase = abase + TILE_B;
        const int k0 = kc * 32;
#pragma unroll
        for (int i = 0; i < 2; i++) {
            const int idx = tid + i * 256;   // 0..511
            const int row = idx >> 2;        // 0..127
            const int seg = idx & 3;         // 16B segment
            const uint32_t soff = (uint32_t)(row * (LDS_H * 2) + seg * 16);
            cp16(abase + soff, A + (long long)row * LDA + k0 + seg * 8);
            cp16(bbase + soff, B + (long long)row * LDB + k0 + seg * 8);
        }
        cp_commit();
    };

    float acc[2][8][4];
#pragma unroll
    for (int mt = 0; mt < 2; mt++)
#pragma unroll
        for (int nt = 0; nt < 8; nt++)
#pragma unroll
            for (int e = 0; e < 4; e++)
                acc[mt][nt][e] = 0.0f;

    load_chunk(0, 0);
    load_chunk(1, 1);

#pragma unroll 1
    for (int c = 0; c < NC; c++) {
        cp_wait<NSTAGE - 2>();
        __syncthreads();
        if (c + NSTAGE - 1 < NC)
            load_chunk((c + NSTAGE - 1) % NSTAGE, c + NSTAGE - 1);

        const uint32_t ab = sb + (c % NSTAGE) * STG_B;
        const uint32_t bb = ab + TILE_B;
#pragma unroll
        for (int ks = 0; ks < 2; ks++) {
            const uint32_t kofs = (uint32_t)((ks * 16 + lc * 8) * 2);
            uint32_t af[2][4];
            uint32_t bf[4][4];
#pragma unroll
            for (int mt = 0; mt < 2; mt++)
                LDSM4(af[mt], ab + (uint32_t)((wm * 32 + mt * 16 + lr) * (LDS_H * 2)) + kofs);
#pragma unroll
            for (int g = 0; g < 4; g++)
                LDSM4(bf[g], bb + (uint32_t)((wn * 64 + g * 16 + lr) * (LDS_H * 2)) + kofs);
#pragma unroll
            for (int mt = 0; mt < 2; mt++)
#pragma unroll
                for (int g = 0; g < 4; g++) {
                    MMA16816(acc[mt][2 * g],     af[mt][0], af[mt][1], af[mt][2], af[mt][3],
                             bf[g][0], bf[g][2]);
                    MMA16816(acc[mt][2 * g + 1], af[mt][0], af[mt][1], af[mt][2], af[mt][3],
                             bf[g][1], bf[g][3]);
                }
        }
    }

    // Epilogue: fused scale+bias (MODE 0), direct float2 stores
    float* D = Dbase + (long long)bz * DBS;
    const int tr = lane >> 2;
    const int tc = (lane & 3) * 2;
    const int mbase = m0 + wm * 32;
    const int nbase = n0 + wn * 64;
#pragma unroll
    for (int mt = 0; mt < 2; mt++)
#pragma unroll
        for (int nt = 0; nt < 8; nt++) {
            float v0 = acc[mt][nt][0], v1 = acc[mt][nt][1];
            float v2 = acc[mt][nt][2], v3 = acc[mt][nt][3];
            if (MODE == 0) {
                const float s = 1.0f / 513.0f;
                v0 = v0 * s + 1.0f;
                v1 = v1 * s + 1.0f;
                v2 = v2 * s + 1.0f;
                v3 = v3 * s + 1.0f;
            }
            const int row = mbase + mt * 16 + tr;
            const int col = nbase + nt * 8 + tc;
            *(float2*)(D + (long long)row * LDD + col)       = make_float2(v0, v1);
            *(float2*)(D + (long long)(row + 8) * LDD + col) = make_float2(v2, v3);
        }
}

// ===========================================================================
// Kernel 4: row softmax over 2048 fp32 (in place) + fp16 copy into g_wh
// ===========================================================================
__global__ void softmax_kernel(float* __restrict__ W)
{
    __shared__ float smax[8];
    __shared__ float ssum[8];
    const size_t row = blockIdx.x;
    float*  p  = W    + row * SEQ;
    __half* ph = g_wh + row * SEQ;
    const int t = threadIdx.x;

    float v[8];
    float m = -1e30f;
#pragma unroll
    for (int i = 0; i < 8; i++) {
        v[i] = p[t + 256 * i];
        m = fmaxf(m, v[i]);
    }
#pragma unroll
    for (int o = 16; o; o >>= 1) m = fmaxf(m, __shfl_xor_sync(0xffffffffu, m, o));
    if ((t & 31) == 0) smax[t >> 5] = m;
    __syncthreads();
    m = smax[0];
#pragma unroll
    for (int i = 1; i < 8; i++) m = fmaxf(m, smax[i]);

    float s = 0.0f;
#pragma unroll
    for (int i = 0; i < 8; i++) {
        v[i] = __expf(v[i] - m);
        s += v[i];
    }
#pragma unroll
    for (int o = 16; o; o >>= 1) s += __shfl_xor_sync(0xffffffffu, s, o);
    if ((t & 31) == 0) ssum[t >> 5] = s;
    __syncthreads();
    s = ssum[0];
#pragma unroll
    for (int i = 1; i < 8; i++) s += ssum[i];
    const float inv = 1.0f / s;

#pragma unroll
    for (int i = 0; i < 8; i++) {
        const float w = v[i] * inv;
        p[t + 256 * i]  = w;
        ph[t + 256 * i] = __float2half(w);
    }
}

// ===========================================================================
// Launch: out = [output (B*S*H fp32) | weights (B*S*S fp32)]
// ===========================================================================
extern "C" void kernel_launch(void* const* d_in, const int* in_sizes, int n_in,
                              void* d_out, int out_size)
{
    const float* Q = (const float*)d_in[0];
    const float* K = (const float*)d_in[1];
    const float* V = (const float*)d_in[2];
    float* out     = (float*)d_out;
    float* weights = out + (size_t)BATCH * SEQ * HID;

    cudaFuncSetAttribute(gemm_hmma<0>, cudaFuncAttributeMaxDynamicSharedMemorySize, GEMM_SMEM);
    cudaFuncSetAttribute(gemm_hmma<1>, cudaFuncAttributeMaxDynamicSharedMemorySize, GEMM_SMEM);

    // 1) phase features for Q and K
    fft_phase_kernel<<<2 * ROWS, 256>>>(Q, K);

    // 2) V -> fp16 transposed [b][h][j]
    {
        dim3 grid(HID / 32, SEQ / 32, BATCH);
        vtrans_kernel<<<grid, dim3(32, 8)>>>(V);
    }

    // 3) scores = QF . KF^T / 513 + 1  (fp32, into weights region)
    {
        dim3 grid(SEQ / 128, SEQ / 128, BATCH);
        gemm_hmma<0><<<grid, 256, GEMM_SMEM>>>(weights);
    }

    // 4) softmax rows in place (+ fp16 copy)
    softmax_kernel<<<ROWS, 256>>>(weights);

    // 5) output = weights @ V
    {
        dim3 grid(SEQ / 128, HID / 128, BATCH);
        gemm_hmma<1><<<grid, 256, GEMM_SMEM>>>(out);
    }
}

// round 6
// speedup vs baseline: 1.3808x; 1.3041x over previous
#include <cuda_runtime.h>
#include <cuda_fp16.h>
#include <stdint.h>

// Problem constants
#define BATCH 4
#define SEQ   2048
#define HID   1024
#define NFREQ 513           // H/2 + 1
#define KD    1088          // 2*NFREQ (=1026) padded to multiple of 32
#define ROWS  (BATCH * SEQ) // 8192

// Scratch (static __device__ — no allocations allowed)
__device__ __align__(256) __half g_qf[(size_t)ROWS * KD];         // Q phase features
__device__ __align__(256) __half g_kf[(size_t)ROWS * KD];         // K phase features
__device__ __align__(256) __half g_wh[(size_t)ROWS * SEQ];        // fp16 softmax weights
__device__ __align__(256) __half g_vt[(size_t)BATCH * HID * SEQ]; // V^T [b][h][j] fp16
__device__ float2 g_tw[768];                                      // W_1024^t, t=0..767

// ===========================================================================
// PTX helpers
// ===========================================================================
__device__ __forceinline__ uint32_t smem_u32(const void* p) {
    uint32_t a;
    asm("{ .reg .u64 t; cvta.to.shared.u64 t, %1; cvt.u32.u64 %0, t; }"
        : "=r"(a) : "l"(p));
    return a;
}
__device__ __forceinline__ void cp16(uint32_t dst, const void* src) {
    asm volatile("cp.async.cg.shared.global [%0], [%1], 16;" :: "r"(dst), "l"(src));
}
__device__ __forceinline__ void cp_commit() {
    asm volatile("cp.async.commit_group;" ::: "memory");
}
template <int N> __device__ __forceinline__ void cp_wait() {
    asm volatile("cp.async.wait_group %0;" :: "n"(N) : "memory");
}

#define LDSM4(r, a)                                                          \
    asm volatile("ldmatrix.sync.aligned.m8n8.x4.shared.b16 {%0,%1,%2,%3}, [%4];" \
                 : "=r"((r)[0]), "=r"((r)[1]), "=r"((r)[2]), "=r"((r)[3])    \
                 : "r"(a))

#define MMA16816(d, a0, a1, a2, a3, b0, b1)                                  \
    asm volatile(                                                            \
        "mma.sync.aligned.m16n8k16.row.col.f32.f16.f16.f32 "                 \
        "{%0,%1,%2,%3}, {%4,%5,%6,%7}, {%8,%9}, {%0,%1,%2,%3};"              \
        : "+f"((d)[0]), "+f"((d)[1]), "+f"((d)[2]), "+f"((d)[3])             \
        : "r"(a0), "r"(a1), "r"(a2), "r"(a3), "r"(b0), "r"(b1))

// ===========================================================================
// Kernel 0: one-time twiddle table W_1024^t = exp(-2*pi*i*t/1024), t<768
// ===========================================================================
__global__ void twiddle_init_kernel()
{
    const int t = blockIdx.x * 256 + threadIdx.x;
    if (t < 768) {
        float s, c;
        sincosf(-6.283185307179586f * (float)t * (1.0f / 1024.0f), &s, &c);
        g_tw[t] = make_float2(c, s);
    }
}

// ===========================================================================
// Kernel 1: per-row FFT-1024 (radix-4 DIF, 5 stages) -> phase features fp16
// cos(phase)=re/|z|, sin(phase)=im/|z|. Natural-order coalesced input,
// digit-reversed smem readout. Padded smem (skew every 16 float2).
// ===========================================================================
#define FPAD(i) ((i) + ((i) >> 4))

__global__ void fft_phase_kernel(const float* __restrict__ Q,
                                 const float* __restrict__ K)
{
    __shared__ float2 sd[1024 + 64];
    __shared__ float2 stw[768];

    const int t = threadIdx.x;                 // 256 threads
    const bool isK = blockIdx.x >= ROWS;
    const int row = blockIdx.x & (ROWS - 1);
    const float* src = (isK ? K : Q) + (size_t)row * HID;
    __half* dst = (isK ? g_kf : g_qf) + (size_t)row * KD;

    // twiddles: global (L2) -> smem
#pragma unroll
    for (int i = t; i < 768; i += 256)
        stw[i] = g_tw[i];

    // natural-order load, imag = 0
    {
        const float4 f = ((const float4*)src)[t];
        sd[FPAD(4 * t + 0)] = make_float2(f.x, 0.0f);
        sd[FPAD(4 * t + 1)] = make_float2(f.y, 0.0f);
        sd[FPAD(4 * t + 2)] = make_float2(f.z, 0.0f);
        sd[FPAD(4 * t + 3)] = make_float2(f.w, 0.0f);
    }
    __syncthreads();

    // 5 radix-4 DIF stages: m = 1024, 256, 64, 16, 4
#pragma unroll
    for (int st = 0; st < 5; st++) {
        const int qlog = 8 - 2 * st;           // log2(q), q = m/4
        const int q    = 1 << qlog;
        const int j    = t & (q - 1);
        const int sub  = t >> qlog;
        const int base = (sub << (qlog + 2)) | j;
        const int tw   = j << (2 * st);        // j * (1024/m)

        const float2 x0 = sd[FPAD(base)];
        const float2 x1 = sd[FPAD(base + q)];
        const float2 x2 = sd[FPAD(base + 2 * q)];
        const float2 x3 = sd[FPAD(base + 3 * q)];

        const float b0r = x0.x + x2.x, b0i = x0.y + x2.y;
        const float b1r = x1.x + x3.x, b1i = x1.y + x3.y;
        const float b2r = x0.x - x2.x, b2i = x0.y - x2.y;
        const float b3r = x1.x - x3.x, b3i = x1.y - x3.y;

        float y0r = b0r + b1r, y0i = b0i + b1i;
        float y1r = b2r + b3i, y1i = b2i - b3r;   // (b2 - i*b3)
        float y2r = b0r - b1r, y2i = b0i - b1i;
        float y3r = b2r - b3i, y3i = b2i + b3r;   // (b2 + i*b3)

        if (st < 4) {                             // last stage: all twiddles = 1
            const float2 w1 = stw[tw];
            const float2 w2 = stw[2 * tw];
            const float2 w3 = stw[3 * tw];
            float r;
            r   = y1r * w1.x - y1i * w1.y;
            y1i = y1r * w1.y + y1i * w1.x;  y1r = r;
            r   = y2r * w2.x - y2i * w2.y;
            y2i = y2r * w2.y + y2i * w2.x;  y2r = r;
            r   = y3r * w3.x - y3i * w3.y;
            y3i = y3r * w3.y + y3i * w3.x;  y3r = r;
        }

        sd[FPAD(base)]         = make_float2(y0r, y0i);
        sd[FPAD(base + q)]     = make_float2(y1r, y1i);
        sd[FPAD(base + 2 * q)] = make_float2(y2r, y2i);
        sd[FPAD(base + 3 * q)] = make_float2(y3r, y3i);
        __syncthreads();
    }

    // readout: X(k) sits at digit-reversed position
    for (int k = t; k < NFREQ; k += 256) {
        const int b10 = __brev((unsigned)k) >> 22;                    // 10-bit reverse
        const int pos = ((b10 & 0x155) << 1) | ((b10 & 0x2AA) >> 1);  // fix pairs
        const float2 z = sd[FPAD(pos)];
        const float mag2 = z.x * z.x + z.y * z.y;
        float cc, ss;
        if (mag2 > 0.0f) {
            const float inv = rsqrtf(mag2);
            cc = z.x * inv;
            ss = z.y * inv;
        } else {
            cc = 1.0f;
            ss = 0.0f;
        }
        dst[k]         = __float2half(cc);
        dst[NFREQ + k] = __float2half(ss);
    }
    for (int k = 2 * NFREQ + t; k < KD; k += 256)
        dst[k] = __float2half(0.0f);
}

// ===========================================================================
// Kernel 2: V [b][j][h] fp32 -> g_vt [b][h][j] fp16 (32x32 smem transpose)
// ===========================================================================
__global__ void vtrans_kernel(const float* __restrict__ V)
{
    __shared__ float s[32][33];
    const int b  = blockIdx.z;
    const int h0 = blockIdx.x * 32;
    const int j0 = blockIdx.y * 32;
    const int tx = threadIdx.x, ty = threadIdx.y;   // 32 x 8

    const float* src = V + ((size_t)b * SEQ + j0) * HID + h0;
#pragma unroll
    for (int r = 0; r < 32; r += 8)
        s[ty + r][tx] = src[(size_t)(ty + r) * HID + tx];
    __syncthreads();

    __half* dst = g_vt + ((size_t)b * HID + h0) * SEQ + j0;
#pragma unroll
    for (int r = 0; r < 32; r += 8)
        dst[(size_t)(ty + r) * SEQ + tx] = __float2half(s[tx][ty + r]);
}

// ===========================================================================
// Kernel 3/5: pipelined HMMA (mma.sync m16n8k16) NT GEMM, 128x128x32 tiles.
// MODE 0: scores = QF.KF^T/513 + 1.  MODE 1: out = W.V  (V pre-transposed).
// 4-stage cp.async ring, smem rows padded to 80B (conflict-free ldmatrix).
// ===========================================================================
#define LDS_H    40                         // halves per smem row (32 + 8 pad)
#define TILE_B   (128 * LDS_H * 2)          // 10240 bytes per operand tile
#define STG_B    (2 * TILE_B)               // 20480 per stage
#define NSTAGE   4
#define GEMM_SMEM (NSTAGE * STG_B)          // 81920

template <int MODE>
__global__ void __launch_bounds__(256, 2) gemm_hmma(float* __restrict__ Dbase)
{
    constexpr int  KT  = (MODE == 0) ? KD : SEQ;
    constexpr int  LDA = (MODE == 0) ? KD : SEQ;
    constexpr int  LDB = (MODE == 0) ? KD : SEQ;
    constexpr long long ABS = (MODE == 0) ? (long long)SEQ * KD : (long long)SEQ * SEQ;
    constexpr long long BBS = (MODE == 0) ? (long long)SEQ * KD : (long long)HID * SEQ;
    constexpr int  LDD = (MODE == 0) ? SEQ : HID;
    constexpr long long DBS = (long long)SEQ * LDD;
    constexpr int  NC  = KT / 32;

    extern __shared__ __align__(256) char smem[];
    const uint32_t sb = smem_u32(smem);

    const int tid  = threadIdx.x;
    const int warp = tid >> 5;
    const int lane = tid & 31;
    const int wm   = warp & 3;              // 4 warps along M (32 rows each)
    const int wn   = warp >> 2;             // 2 warps along N (64 cols each)
    const int m0 = blockIdx.x * 128;
    const int n0 = blockIdx.y * 128;
    const int bz = blockIdx.z;

    const __half* A = ((MODE == 0) ? g_qf : g_wh) + (long long)bz * ABS + (long long)m0 * LDA;
    const __half* B = ((MODE == 0) ? g_kf : g_vt) + (long long)bz * BBS + (long long)n0 * LDB;

    const int lr = lane & 15;
    const int lc = lane >> 4;

    auto load_chunk = [&](int st, int kc) {
        const uint32_t abase = sb + st * STG_B;
        const uint32_t bbase = abase + TILE_B;
        const int k0 = kc * 32;
#pragma unroll
        for (int i = 0; i < 2; i++) {
            const int idx = tid + i * 256;   // 0..511
            const int row = idx >> 2;        // 0..127
            const int seg = idx & 3;         // 16B segment
            const uint32_t soff = (uint32_t)(row * (LDS_H * 2) + seg * 16);
            cp16(abase + soff, A + (long long)row * LDA + k0 + seg * 8);
            cp16(bbase + soff, B + (long long)row * LDB + k0 + seg * 8);
        }
        cp_commit();
    };

    float acc[2][8][4];
#pragma unroll
    for (int mt = 0; mt < 2; mt++)
#pragma unroll
        for (int nt = 0; nt < 8; nt++)
#pragma unroll
            for (int e = 0; e < 4; e++)
                acc[mt][nt][e] = 0.0f;

    load_chunk(0, 0);
    load_chunk(1, 1);
    load_chunk(2, 2);

#pragma unroll 1
    for (int c = 0; c < NC; c++) {
        if (c + NSTAGE - 1 < NC) cp_wait<NSTAGE - 2>(); else cp_wait<0>();
        __syncthreads();
        if (c + NSTAGE - 1 < NC)
            load_chunk((c + NSTAGE - 1) % NSTAGE, c + NSTAGE - 1);

        const uint32_t ab = sb + (c % NSTAGE) * STG_B;
        const uint32_t bb = ab + TILE_B;
#pragma unroll
        for (int ks = 0; ks < 2; ks++) {
            const uint32_t kofs = (uint32_t)((ks * 16 + lc * 8) * 2);
            uint32_t af[2][4];
            uint32_t bf[4][4];
#pragma unroll
            for (int mt = 0; mt < 2; mt++)
                LDSM4(af[mt], ab + (uint32_t)((wm * 32 + mt * 16 + lr) * (LDS_H * 2)) + kofs);
#pragma unroll
            for (int g = 0; g < 4; g++)
                LDSM4(bf[g], bb + (uint32_t)((wn * 64 + g * 16 + lr) * (LDS_H * 2)) + kofs);
#pragma unroll
            for (int mt = 0; mt < 2; mt++)
#pragma unroll
                for (int g = 0; g < 4; g++) {
                    MMA16816(acc[mt][2 * g],     af[mt][0], af[mt][1], af[mt][2], af[mt][3],
                             bf[g][0], bf[g][2]);
                    MMA16816(acc[mt][2 * g + 1], af[mt][0], af[mt][1], af[mt][2], af[mt][3],
                             bf[g][1], bf[g][3]);
                }
        }
    }

    // Epilogue: fused scale+bias (MODE 0), direct float2 stores
    float* D = Dbase + (long long)bz * DBS;
    const int tr = lane >> 2;
    const int tc = (lane & 3) * 2;
    const int mbase = m0 + wm * 32;
    const int nbase = n0 + wn * 64;
#pragma unroll
    for (int mt = 0; mt < 2; mt++)
#pragma unroll
        for (int nt = 0; nt < 8; nt++) {
            float v0 = acc[mt][nt][0], v1 = acc[mt][nt][1];
            float v2 = acc[mt][nt][2], v3 = acc[mt][nt][3];
            if (MODE == 0) {
                const float s = 1.0f / 513.0f;
                v0 = v0 * s + 1.0f;
                v1 = v1 * s + 1.0f;
                v2 = v2 * s + 1.0f;
                v3 = v3 * s + 1.0f;
            }
            const int row = mbase + mt * 16 + tr;
            const int col = nbase + nt * 8 + tc;
            *(float2*)(D + (long long)row * LDD + col)       = make_float2(v0, v1);
            *(float2*)(D + (long long)(row + 8) * LDD + col) = make_float2(v2, v3);
        }
}

// ===========================================================================
// Kernel 4: row softmax over 2048 fp32 (in place) + fp16 copy into g_wh
// ===========================================================================
__global__ void softmax_kernel(float* __restrict__ W)
{
    __shared__ float smax[8];
    __shared__ float ssum[8];
    const size_t row = blockIdx.x;
    float*  p  = W    + row * SEQ;
    __half* ph = g_wh + row * SEQ;
    const int t = threadIdx.x;

    float v[8];
    float m = -1e30f;
#pragma unroll
    for (int i = 0; i < 8; i++) {
        v[i] = p[t + 256 * i];
        m = fmaxf(m, v[i]);
    }
#pragma unroll
    for (int o = 16; o; o >>= 1) m = fmaxf(m, __shfl_xor_sync(0xffffffffu, m, o));
    if ((t & 31) == 0) smax[t >> 5] = m;
    __syncthreads();
    m = smax[0];
#pragma unroll
    for (int i = 1; i < 8; i++) m = fmaxf(m, smax[i]);

    float s = 0.0f;
#pragma unroll
    for (int i = 0; i < 8; i++) {
        v[i] = __expf(v[i] - m);
        s += v[i];
    }
#pragma unroll
    for (int o = 16; o; o >>= 1) s += __shfl_xor_sync(0xffffffffu, s, o);
    if ((t & 31) == 0) ssum[t >> 5] = s;
    __syncthreads();
    s = ssum[0];
#pragma unroll
    for (int i = 1; i < 8; i++) s += ssum[i];
    const float inv = 1.0f / s;

#pragma unroll
    for (int i = 0; i < 8; i++) {
        const float w = v[i] * inv;
        p[t + 256 * i]  = w;
        ph[t + 256 * i] = __float2half(w);
    }
}

// ===========================================================================
// Launch: out = [output (B*S*H fp32) | weights (B*S*S fp32)]
// ===========================================================================
extern "C" void kernel_launch(void* const* d_in, const int* in_sizes, int n_in,
                              void* d_out, int out_size)
{
    const float* Q = (const float*)d_in[0];
    const float* K = (const float*)d_in[1];
    const float* V = (const float*)d_in[2];
    float* out     = (float*)d_out;
    float* weights = out + (size_t)BATCH * SEQ * HID;

    cudaFuncSetAttribute(gemm_hmma<0>, cudaFuncAttributeMaxDynamicSharedMemorySize, GEMM_SMEM);
    cudaFuncSetAttribute(gemm_hmma<1>, cudaFuncAttributeMaxDynamicSharedMemorySize, GEMM_SMEM);

    // 0) twiddle table (once per launch; tiny)
    twiddle_init_kernel<<<3, 256>>>();

    // 1) phase features for Q and K
    fft_phase_kernel<<<2 * ROWS, 256>>>(Q, K);

    // 2) V -> fp16 transposed [b][h][j]
    {
        dim3 grid(HID / 32, SEQ / 32, BATCH);
        vtrans_kernel<<<grid, dim3(32, 8)>>>(V);
    }

    // 3) scores = QF . KF^T / 513 + 1  (fp32, into weights region)
    {
        dim3 grid(SEQ / 128, SEQ / 128, BATCH);
        gemm_hmma<0><<<grid, 256, GEMM_SMEM>>>(weights);
    }

    // 4) softmax rows in place (+ fp16 copy)
    softmax_kernel<<<ROWS, 256>>>(weights);

    // 5) output = weights @ V
    {
        dim3 grid(SEQ / 128, HID / 128, BATCH);
        gemm_hmma<1><<<grid, 256, GEMM_SMEM>>>(out);
    }
}

// round 8
// speedup vs baseline: 1.5039x; 1.0891x over previous
#include <cuda_runtime.h>
#include <cuda_fp16.h>
#include <stdint.h>

// Problem constants
#define BATCH 4
#define SEQ   2048
#define HID   1024
#define NFREQ 513           // H/2 + 1
#define KD    1088          // 2*NFREQ (=1026) padded to multiple of 32
#define ROWS  (BATCH * SEQ) // 8192

// Scratch (static __device__ — no allocations allowed)
__device__ __align__(256) __half g_qf[(size_t)ROWS * KD];         // Q phase features
__device__ __align__(256) __half g_kf[(size_t)ROWS * KD];         // K phase features
__device__ __align__(256) __half g_wh[(size_t)ROWS * SEQ];        // fp16 softmax weights
__device__ __align__(256) __half g_vt[(size_t)BATCH * HID * SEQ]; // V^T [b][h][j] fp16
__device__ float2 g_tw[768];                                      // W_1024^t, t=0..767

// ===========================================================================
// PTX helpers
// ===========================================================================
__device__ __forceinline__ uint32_t smem_u32(const void* p) {
    uint32_t a;
    asm("{ .reg .u64 t; cvta.to.shared.u64 t, %1; cvt.u32.u64 %0, t; }"
        : "=r"(a) : "l"(p));
    return a;
}
__device__ __forceinline__ void cp16(uint32_t dst, const void* src) {
    asm volatile("cp.async.cg.shared.global [%0], [%1], 16;" :: "r"(dst), "l"(src));
}
__device__ __forceinline__ void cp_commit() {
    asm volatile("cp.async.commit_group;" ::: "memory");
}
template <int N> __device__ __forceinline__ void cp_wait() {
    asm volatile("cp.async.wait_group %0;" :: "n"(N) : "memory");
}

#define LDSM4(r, a)                                                          \
    asm volatile("ldmatrix.sync.aligned.m8n8.x4.shared.b16 {%0,%1,%2,%3}, [%4];" \
                 : "=r"((r)[0]), "=r"((r)[1]), "=r"((r)[2]), "=r"((r)[3])    \
                 : "r"(a))

#define MMA16816(d, a0, a1, a2, a3, b0, b1)                                  \
    asm volatile(                                                            \
        "mma.sync.aligned.m16n8k16.row.col.f32.f16.f16.f32 "                 \
        "{%0,%1,%2,%3}, {%4,%5,%6,%7}, {%8,%9}, {%0,%1,%2,%3};"              \
        : "+f"((d)[0]), "+f"((d)[1]), "+f"((d)[2]), "+f"((d)[3])             \
        : "r"(a0), "r"(a1), "r"(a2), "r"(a3), "r"(b0), "r"(b1))

// ===========================================================================
// Kernel 0: one-time twiddle table W_1024^t = exp(-2*pi*i*t/1024), t<768
// ===========================================================================
__global__ void twiddle_init_kernel()
{
    const int t = blockIdx.x * 256 + threadIdx.x;
    if (t < 768) {
        float s, c;
        sincosf(-6.283185307179586f * (float)t * (1.0f / 1024.0f), &s, &c);
        g_tw[t] = make_float2(c, s);
    }
}

// ===========================================================================
// Kernel 1: two real rows per block packed into ONE complex FFT-1024
// (radix-4 DIF, 5 stages). z = rowA + i*rowB; untangle at readout:
//   X_A(k) = (Z(k) + conj(Z(N-k)))          (scale cancels in normalization)
//   X_B(k) = (Z(k) - conj(Z(N-k))) / i
// cos(phase)=re/|z|, sin(phase)=im/|z|.
// ===========================================================================
#define FPAD(i) ((i) + ((i) >> 4))

__global__ void fft_phase_kernel(const float* __restrict__ Q,
                                 const float* __restrict__ K)
{
    __shared__ float2 sd[1024 + 64];
    __shared__ float2 stw[768];

    const int t = threadIdx.x;                 // 256 threads
    const bool isK = blockIdx.x >= (ROWS / 2);
    const int pr = blockIdx.x & (ROWS / 2 - 1);
    const float* srcA = (isK ? K : Q) + (size_t)(2 * pr) * HID;
    const float* srcB = srcA + HID;
    __half* dstA = (isK ? g_kf : g_qf) + (size_t)(2 * pr) * KD;
    __half* dstB = dstA + KD;

    // twiddles: global (L2) -> smem
#pragma unroll
    for (int i = t; i < 768; i += 256)
        stw[i] = g_tw[i];

    // natural-order load: rowA -> re, rowB -> im
    {
        const float4 fa = ((const float4*)srcA)[t];
        const float4 fb = ((const float4*)srcB)[t];
        sd[FPAD(4 * t + 0)] = make_float2(fa.x, fb.x);
        sd[FPAD(4 * t + 1)] = make_float2(fa.y, fb.y);
        sd[FPAD(4 * t + 2)] = make_float2(fa.z, fb.z);
        sd[FPAD(4 * t + 3)] = make_float2(fa.w, fb.w);
    }
    __syncthreads();

    // 5 radix-4 DIF stages
#pragma unroll
    for (int st = 0; st < 5; st++) {
        const int qlog = 8 - 2 * st;           // log2(q), q = m/4
        const int q    = 1 << qlog;
        const int j    = t & (q - 1);
        const int sub  = t >> qlog;
        const int base = (sub << (qlog + 2)) | j;
        const int tw   = j << (2 * st);

        const float2 x0 = sd[FPAD(base)];
        const float2 x1 = sd[FPAD(base + q)];
        const float2 x2 = sd[FPAD(base + 2 * q)];
        const float2 x3 = sd[FPAD(base + 3 * q)];

        const float b0r = x0.x + x2.x, b0i = x0.y + x2.y;
        const float b1r = x1.x + x3.x, b1i = x1.y + x3.y;
        const float b2r = x0.x - x2.x, b2i = x0.y - x2.y;
        const float b3r = x1.x - x3.x, b3i = x1.y - x3.y;

        float y0r = b0r + b1r, y0i = b0i + b1i;
        float y1r = b2r + b3i, y1i = b2i - b3r;
        float y2r = b0r - b1r, y2i = b0i - b1i;
        float y3r = b2r - b3i, y3i = b2i + b3r;

        if (st < 4) {
            const float2 w1 = stw[tw];
            const float2 w2 = stw[2 * tw];
            const float2 w3 = stw[3 * tw];
            float r;
            r   = y1r * w1.x - y1i * w1.y;
            y1i = y1r * w1.y + y1i * w1.x;  y1r = r;
            r   = y2r * w2.x - y2i * w2.y;
            y2i = y2r * w2.y + y2i * w2.x;  y2r = r;
            r   = y3r * w3.x - y3i * w3.y;
            y3i = y3r * w3.y + y3i * w3.x;  y3r = r;
        }

        sd[FPAD(base)]         = make_float2(y0r, y0i);
        sd[FPAD(base + q)]     = make_float2(y1r, y1i);
        sd[FPAD(base + 2 * q)] = make_float2(y2r, y2i);
        sd[FPAD(base + 3 * q)] = make_float2(y3r, y3i);
        __syncthreads();
    }

    // readout + untangle: Z(k) sits at digit-reversed position
    for (int k = t; k < NFREQ; k += 256) {
        const int kb  = (1024 - k) & 1023;
        const int ra  = __brev((unsigned)k)  >> 22;
        const int rb  = __brev((unsigned)kb) >> 22;
        const int pa  = ((ra & 0x155) << 1) | ((ra & 0x2AA) >> 1);
        const int pb  = ((rb & 0x155) << 1) | ((rb & 0x2AA) >> 1);
        const float2 za = sd[FPAD(pa)];
        const float2 zb = sd[FPAD(pb)];

        // X_A = (za + conj(zb)),  X_B = (za - conj(zb))/i  (scale dropped)
        const float ar = za.x + zb.x;
        const float ai = za.y - zb.y;
        const float br = za.y + zb.y;
        const float bi = zb.x - za.x;

        {
            const float m2 = ar * ar + ai * ai;
            float cc = 1.0f, ss = 0.0f;
            if (m2 > 0.0f) {
                const float inv = rsqrtf(m2);
                cc = ar * inv;
                ss = ai * inv;
            }
            dstA[k]         = __float2half(cc);
            dstA[NFREQ + k] = __float2half(ss);
        }
        {
            const float m2 = br * br + bi * bi;
            float cc = 1.0f, ss = 0.0f;
            if (m2 > 0.0f) {
                const float inv = rsqrtf(m2);
                cc = br * inv;
                ss = bi * inv;
            }
            dstB[k]         = __float2half(cc);
            dstB[NFREQ + k] = __float2half(ss);
        }
    }
    for (int k = 2 * NFREQ + t; k < KD; k += 256) {
        dstA[k] = __float2half(0.0f);
        dstB[k] = __float2half(0.0f);
    }
}

// ===========================================================================
// Kernel 2: V [b][j][h] fp32 -> g_vt [b][h][j] fp16 (32x32 smem transpose)
// ===========================================================================
__global__ void vtrans_kernel(const float* __restrict__ V)
{
    __shared__ float s[32][33];
    const int b  = blockIdx.z;
    const int h0 = blockIdx.x * 32;
    const int j0 = blockIdx.y * 32;
    const int tx = threadIdx.x, ty = threadIdx.y;   // 32 x 8

    const float* src = V + ((size_t)b * SEQ + j0) * HID + h0;
#pragma unroll
    for (int r = 0; r < 32; r += 8)
        s[ty + r][tx] = src[(size_t)(ty + r) * HID + tx];
    __syncthreads();

    __half* dst = g_vt + ((size_t)b * HID + h0) * SEQ + j0;
#pragma unroll
    for (int r = 0; r < 32; r += 8)
        dst[(size_t)(ty + r) * SEQ + tx] = __float2half(s[tx][ty + r]);
}

// ===========================================================================
// Kernel 3/5: pipelined HMMA NT GEMM, 128x256x32 CTA tiles, 8 warps (2Mx4N),
// 64x64 warp tiles. MODE 0: scores = QF.KF^T/513 + 1. MODE 1: out = W.V.
// 4-stage cp.async ring, smem rows padded to 80B (conflict-free ldmatrix).
// ===========================================================================
#define LDS_H    40                          // halves per smem row (32 + 8 pad)
#define A_TILE_B (128 * LDS_H * 2)           // 10240
#define B_TILE_B (256 * LDS_H * 2)           // 20480
#define STG_B    (A_TILE_B + B_TILE_B)       // 30720
#define NSTAGE   4
#define GEMM_SMEM (NSTAGE * STG_B)           // 122880

template <int MODE>
__global__ void __launch_bounds__(256, 1) gemm_hmma(float* __restrict__ Dbase)
{
    constexpr int  KT  = (MODE == 0) ? KD : SEQ;
    constexpr int  LDA = (MODE == 0) ? KD : SEQ;
    constexpr int  LDB = (MODE == 0) ? KD : SEQ;
    constexpr long long ABS = (MODE == 0) ? (long long)SEQ * KD : (long long)SEQ * SEQ;
    constexpr long long BBS = (MODE == 0) ? (long long)SEQ * KD : (long long)HID * SEQ;
    constexpr int  LDD = (MODE == 0) ? SEQ : HID;
    constexpr long long DBS = (long long)SEQ * LDD;
    constexpr int  NC  = KT / 32;

    extern __shared__ __align__(256) char smem[];
    const uint32_t sb = smem_u32(smem);

    const int tid  = threadIdx.x;
    const int warp = tid >> 5;
    const int lane = tid & 31;
    const int wm   = warp & 1;               // 2 warps along M (64 rows each)
    const int wn   = warp >> 1;              // 4 warps along N (64 cols each)
    const int m0 = blockIdx.x * 128;
    const int n0 = blockIdx.y * 256;
    const int bz = blockIdx.z;

    const __half* A = ((MODE == 0) ? g_qf : g_wh) + (long long)bz * ABS + (long long)m0 * LDA;
    const __half* B = ((MODE == 0) ? g_kf : g_vt) + (long long)bz * BBS + (long long)n0 * LDB;

    const int lr = lane & 15;
    const int lc = lane >> 4;

    auto load_chunk = [&](int st, int kc) {
        const uint32_t abase = sb + st * STG_B;
        const uint32_t bbase = abase + A_TILE_B;
        const int k0 = kc * 32;
#pragma unroll
        for (int i = 0; i < 2; i++) {          // A: 128 rows x 4 segs
            const int idx = tid + i * 256;
            const int row = idx >> 2;
            const int seg = idx & 3;
            cp16(abase + (uint32_t)(row * (LDS_H * 2) + seg * 16),
                 A + (long long)row * LDA + k0 + seg * 8);
        }
#pragma unroll
        for (int i = 0; i < 4; i++) {          // B: 256 rows x 4 segs
            const int idx = tid + i * 256;
            const int row = idx >> 2;
            const int seg = idx & 3;
            cp16(bbase + (uint32_t)(row * (LDS_H * 2) + seg * 16),
                 B + (long long)row * LDB + k0 + seg * 8);
        }
        cp_commit();
    };

    float acc[4][8][4];
#pragma unroll
    for (int mt = 0; mt < 4; mt++)
#pragma unroll
        for (int nt = 0; nt < 8; nt++)
#pragma unroll
            for (int e = 0; e < 4; e++)
                acc[mt][nt][e] = 0.0f;

    load_chunk(0, 0);
    load_chunk(1, 1);
    load_chunk(2, 2);

#pragma unroll 1
    for (int c = 0; c < NC; c++) {
        if (c + NSTAGE - 1 < NC) cp_wait<NSTAGE - 2>(); else cp_wait<0>();
        __syncthreads();
        if (c + NSTAGE - 1 < NC)
            load_chunk((c + NSTAGE - 1) % NSTAGE, c + NSTAGE - 1);

        const uint32_t ab = sb + (c % NSTAGE) * STG_B;
        const uint32_t bb = ab + A_TILE_B;
#pragma unroll
        for (int ks = 0; ks < 2; ks++) {
            const uint32_t kofs = (uint32_t)((ks * 16 + lc * 8) * 2);
            uint32_t af[4][4];
            uint32_t bf[4][4];
#pragma unroll
            for (int mt = 0; mt < 4; mt++)
                LDSM4(af[mt], ab + (uint32_t)((wm * 64 + mt * 16 + lr) * (LDS_H * 2)) + kofs);
#pragma unroll
            for (int g = 0; g < 4; g++)
                LDSM4(bf[g], bb + (uint32_t)((wn * 64 + g * 16 + lr) * (LDS_H * 2)) + kofs);
#pragma unroll
            for (int mt = 0; mt < 4; mt++)
#pragma unroll
                for (int g = 0; g < 4; g++) {
                    MMA16816(acc[mt][2 * g],     af[mt][0], af[mt][1], af[mt][2], af[mt][3],
                             bf[g][0], bf[g][2]);
                    MMA16816(acc[mt][2 * g + 1], af[mt][0], af[mt][1], af[mt][2], af[mt][3],
                             bf[g][1], bf[g][3]);
                }
        }
    }

    // Epilogue: fused scale+bias (MODE 0), direct float2 stores
    float* D = Dbase + (long long)bz * DBS;
    const int tr = lane >> 2;
    const int tc = (lane & 3) * 2;
    const int mbase = m0 + wm * 64;
    const int nbase = n0 + wn * 64;
#pragma unroll
    for (int mt = 0; mt < 4; mt++)
#pragma unroll
        for (int nt = 0; nt < 8; nt++) {
            float v0 = acc[mt][nt][0], v1 = acc[mt][nt][1];
            float v2 = acc[mt][nt][2], v3 = acc[mt][nt][3];
            if (MODE == 0) {
                const float s = 1.0f / 513.0f;
                v0 = v0 * s + 1.0f;
                v1 = v1 * s + 1.0f;
                v2 = v2 * s + 1.0f;
                v3 = v3 * s + 1.0f;
            }
            const int row = mbase + mt * 16 + tr;
            const int col = nbase + nt * 8 + tc;
            *(float2*)(D + (long long)row * LDD + col)       = make_float2(v0, v1);
            *(float2*)(D + (long long)(row + 8) * LDD + col) = make_float2(v2, v3);
        }
}

// ===========================================================================
// Kernel 4: row softmax over 2048 fp32 (in place) + fp16 copy into g_wh
// ===========================================================================
__global__ void softmax_kernel(float* __restrict__ W)
{
    __shared__ float smax[8];
    __shared__ float ssum[8];
    const size_t row = blockIdx.x;
    float*  p  = W    + row * SEQ;
    __half* ph = g_wh + row * SEQ;
    const int t = threadIdx.x;

    float v[8];
    float m = -1e30f;
#pragma unroll
    for (int i = 0; i < 8; i++) {
        v[i] = p[t + 256 * i];
        m = fmaxf(m, v[i]);
    }
#pragma unroll
    for (int o = 16; o; o >>= 1) m = fmaxf(m, __shfl_xor_sync(0xffffffffu, m, o));
    if ((t & 31) == 0) smax[t >> 5] = m;
    __syncthreads();
    m = smax[0];
#pragma unroll
    for (int i = 1; i < 8; i++) m = fmaxf(m, smax[i]);

    float s = 0.0f;
#pragma unroll
    for (int i = 0; i < 8; i++) {
        v[i] = __expf(v[i] - m);
        s += v[i];
    }
#pragma unroll
    for (int o = 16; o; o >>= 1) s += __shfl_xor_sync(0xffffffffu, s, o);
    if ((t & 31) == 0) ssum[t >> 5] = s;
    __syncthreads();
    s = ssum[0];
#pragma unroll
    for (int i = 1; i < 8; i++) s += ssum[i];
    const float inv = 1.0f / s;

#pragma unroll
    for (int i = 0; i < 8; i++) {
        const float w = v[i] * inv;
        p[t + 256 * i]  = w;
        ph[t + 256 * i] = __float2half(w);
    }
}

// ===========================================================================
// Launch: out = [output (B*S*H fp32) | weights (B*S*S fp32)]
// ===========================================================================
extern "C" void kernel_launch(void* const* d_in, const int* in_sizes, int n_in,
                              void* d_out, int out_size)
{
    const float* Q = (const float*)d_in[0];
    const float* K = (const float*)d_in[1];
    const float* V = (const float*)d_in[2];
    float* out     = (float*)d_out;
    float* weights = out + (size_t)BATCH * SEQ * HID;

    cudaFuncSetAttribute(gemm_hmma<0>, cudaFuncAttributeMaxDynamicSharedMemorySize, GEMM_SMEM);
    cudaFuncSetAttribute(gemm_hmma<1>, cudaFuncAttributeMaxDynamicSharedMemorySize, GEMM_SMEM);

    // 0) twiddle table (once per launch; tiny)
    twiddle_init_kernel<<<3, 256>>>();

    // 1) phase features for Q and K (two rows per block)
    fft_phase_kernel<<<ROWS, 256>>>(Q, K);

    // 2) V -> fp16 transposed [b][h][j]
    {
        dim3 grid(HID / 32, SEQ / 32, BATCH);
        vtrans_kernel<<<grid, dim3(32, 8)>>>(V);
    }

    // 3) scores = QF . KF^T / 513 + 1  (fp32, into weights region)
    {
        dim3 grid(SEQ / 128, SEQ / 256, BATCH);
        gemm_hmma<0><<<grid, 256, GEMM_SMEM>>>(weights);
    }

    // 4) softmax rows in place (+ fp16 copy)
    softmax_kernel<<<ROWS, 256>>>(weights);

    // 5) output = weights @ V
    {
        dim3 grid(SEQ / 128, HID / 256, BATCH);
        gemm_hmma<1><<<grid, 256, GEMM_SMEM>>>(out);
    }
}

// round 9
// speedup vs baseline: 1.5632x; 1.0394x over previous
#include <cuda_runtime.h>
#include <cuda_fp16.h>
#include <stdint.h>

// Problem constants
#define BATCH 4
#define SEQ   2048
#define HID   1024
#define NFREQ 513           // H/2 + 1
#define KD    1088          // 2*NFREQ (=1026) padded to multiple of 32
#define ROWS  (BATCH * SEQ) // 8192

// Scratch (static __device__ — no allocations allowed)
__device__ __align__(256) __half g_qf[(size_t)ROWS * KD];         // Q phase features
__device__ __align__(256) __half g_kf[(size_t)ROWS * KD];         // K phase features
__device__ __align__(256) __half g_wh[(size_t)ROWS * SEQ];        // fp16 softmax weights
__device__ __align__(256) __half g_vt[(size_t)BATCH * HID * SEQ]; // V^T [b][h][j] fp16
__device__ float2 g_tw[768];                                      // W_1024^t, t=0..767

// ===========================================================================
// PTX helpers
// ===========================================================================
__device__ __forceinline__ uint32_t smem_u32(const void* p) {
    uint32_t a;
    asm("{ .reg .u64 t; cvta.to.shared.u64 t, %1; cvt.u32.u64 %0, t; }"
        : "=r"(a) : "l"(p));
    return a;
}
__device__ __forceinline__ void cp16(uint32_t dst, const void* src) {
    asm volatile("cp.async.cg.shared.global [%0], [%1], 16;" :: "r"(dst), "l"(src));
}
__device__ __forceinline__ void cp_commit() {
    asm volatile("cp.async.commit_group;" ::: "memory");
}
template <int N> __device__ __forceinline__ void cp_wait() {
    asm volatile("cp.async.wait_group %0;" :: "n"(N) : "memory");
}

#define LDSM4(r, a)                                                          \
    asm volatile("ldmatrix.sync.aligned.m8n8.x4.shared.b16 {%0,%1,%2,%3}, [%4];" \
                 : "=r"((r)[0]), "=r"((r)[1]), "=r"((r)[2]), "=r"((r)[3])    \
                 : "r"(a))

#define MMA16816(d, a0, a1, a2, a3, b0, b1)                                  \
    asm volatile(                                                            \
        "mma.sync.aligned.m16n8k16.row.col.f32.f16.f16.f32 "                 \
        "{%0,%1,%2,%3}, {%4,%5,%6,%7}, {%8,%9}, {%0,%1,%2,%3};"              \
        : "+f"((d)[0]), "+f"((d)[1]), "+f"((d)[2]), "+f"((d)[3])             \
        : "r"(a0), "r"(a1), "r"(a2), "r"(a3), "r"(b0), "r"(b1))

// ===========================================================================
// Kernel 0: one-time twiddle table W_1024^t = exp(-2*pi*i*t/1024), t<768
// ===========================================================================
__global__ void twiddle_init_kernel()
{
    const int t = blockIdx.x * 256 + threadIdx.x;
    if (t < 768) {
        float s, c;
        sincosf(-6.283185307179586f * (float)t * (1.0f / 1024.0f), &s, &c);
        g_tw[t] = make_float2(c, s);
    }
}

// ===========================================================================
// Kernel 1: two real rows per block packed into ONE complex FFT-1024
// (radix-4 DIF, 5 stages), untangle at readout.
// ===========================================================================
#define FPAD(i) ((i) + ((i) >> 4))

__global__ void fft_phase_kernel(const float* __restrict__ Q,
                                 const float* __restrict__ K)
{
    __shared__ float2 sd[1024 + 64];
    __shared__ float2 stw[768];

    const int t = threadIdx.x;                 // 256 threads
    const bool isK = blockIdx.x >= (ROWS / 2);
    const int pr = blockIdx.x & (ROWS / 2 - 1);
    const float* srcA = (isK ? K : Q) + (size_t)(2 * pr) * HID;
    const float* srcB = srcA + HID;
    __half* dstA = (isK ? g_kf : g_qf) + (size_t)(2 * pr) * KD;
    __half* dstB = dstA + KD;

#pragma unroll
    for (int i = t; i < 768; i += 256)
        stw[i] = g_tw[i];

    {
        const float4 fa = ((const float4*)srcA)[t];
        const float4 fb = ((const float4*)srcB)[t];
        sd[FPAD(4 * t + 0)] = make_float2(fa.x, fb.x);
        sd[FPAD(4 * t + 1)] = make_float2(fa.y, fb.y);
        sd[FPAD(4 * t + 2)] = make_float2(fa.z, fb.z);
        sd[FPAD(4 * t + 3)] = make_float2(fa.w, fb.w);
    }
    __syncthreads();

#pragma unroll
    for (int st = 0; st < 5; st++) {
        const int qlog = 8 - 2 * st;
        const int q    = 1 << qlog;
        const int j    = t & (q - 1);
        const int sub  = t >> qlog;
        const int base = (sub << (qlog + 2)) | j;
        const int tw   = j << (2 * st);

        const float2 x0 = sd[FPAD(base)];
        const float2 x1 = sd[FPAD(base + q)];
        const float2 x2 = sd[FPAD(base + 2 * q)];
        const float2 x3 = sd[FPAD(base + 3 * q)];

        const float b0r = x0.x + x2.x, b0i = x0.y + x2.y;
        const float b1r = x1.x + x3.x, b1i = x1.y + x3.y;
        const float b2r = x0.x - x2.x, b2i = x0.y - x2.y;
        const float b3r = x1.x - x3.x, b3i = x1.y - x3.y;

        float y0r = b0r + b1r, y0i = b0i + b1i;
        float y1r = b2r + b3i, y1i = b2i - b3r;
        float y2r = b0r - b1r, y2i = b0i - b1i;
        float y3r = b2r - b3i, y3i = b2i + b3r;

        if (st < 4) {
            const float2 w1 = stw[tw];
            const float2 w2 = stw[2 * tw];
            const float2 w3 = stw[3 * tw];
            float r;
            r   = y1r * w1.x - y1i * w1.y;
            y1i = y1r * w1.y + y1i * w1.x;  y1r = r;
            r   = y2r * w2.x - y2i * w2.y;
            y2i = y2r * w2.y + y2i * w2.x;  y2r = r;
            r   = y3r * w3.x - y3i * w3.y;
            y3i = y3r * w3.y + y3i * w3.x;  y3r = r;
        }

        sd[FPAD(base)]         = make_float2(y0r, y0i);
        sd[FPAD(base + q)]     = make_float2(y1r, y1i);
        sd[FPAD(base + 2 * q)] = make_float2(y2r, y2i);
        sd[FPAD(base + 3 * q)] = make_float2(y3r, y3i);
        __syncthreads();
    }

    for (int k = t; k < NFREQ; k += 256) {
        const int kb  = (1024 - k) & 1023;
        const int ra  = __brev((unsigned)k)  >> 22;
        const int rb  = __brev((unsigned)kb) >> 22;
        const int pa  = ((ra & 0x155) << 1) | ((ra & 0x2AA) >> 1);
        const int pb  = ((rb & 0x155) << 1) | ((rb & 0x2AA) >> 1);
        const float2 za = sd[FPAD(pa)];
        const float2 zb = sd[FPAD(pb)];

        const float ar = za.x + zb.x;
        const float ai = za.y - zb.y;
        const float br = za.y + zb.y;
        const float bi = zb.x - za.x;

        {
            const float m2 = ar * ar + ai * ai;
            float cc = 1.0f, ss = 0.0f;
            if (m2 > 0.0f) {
                const float inv = rsqrtf(m2);
                cc = ar * inv;
                ss = ai * inv;
            }
            dstA[k]         = __float2half(cc);
            dstA[NFREQ + k] = __float2half(ss);
        }
        {
            const float m2 = br * br + bi * bi;
            float cc = 1.0f, ss = 0.0f;
            if (m2 > 0.0f) {
                const float inv = rsqrtf(m2);
                cc = br * inv;
                ss = bi * inv;
            }
            dstB[k]         = __float2half(cc);
            dstB[NFREQ + k] = __float2half(ss);
        }
    }
    for (int k = 2 * NFREQ + t; k < KD; k += 256) {
        dstA[k] = __float2half(0.0f);
        dstB[k] = __float2half(0.0f);
    }
}

// ===========================================================================
// Kernel 2: V [b][j][h] fp32 -> g_vt [b][h][j] fp16 (32x32 smem transpose)
// ===========================================================================
__global__ void vtrans_kernel(const float* __restrict__ V)
{
    __shared__ float s[32][33];
    const int b  = blockIdx.z;
    const int h0 = blockIdx.x * 32;
    const int j0 = blockIdx.y * 32;
    const int tx = threadIdx.x, ty = threadIdx.y;   // 32 x 8

    const float* src = V + ((size_t)b * SEQ + j0) * HID + h0;
#pragma unroll
    for (int r = 0; r < 32; r += 8)
        s[ty + r][tx] = src[(size_t)(ty + r) * HID + tx];
    __syncthreads();

    __half* dst = g_vt + ((size_t)b * HID + h0) * SEQ + j0;
#pragma unroll
    for (int r = 0; r < 32; r += 8)
        dst[(size_t)(ty + r) * SEQ + tx] = __float2half(s[tx][ty + r]);
}

// ===========================================================================
// Kernel 3/5: pipelined HMMA NT GEMM, 128x128x32 CTA tiles, 4 warps (2x2),
// 64x64 warp tiles, 128 threads, 2 CTAs/SM (reg budget 256).
// MODE 0: scores = QF.KF^T/513 + 1.  MODE 1: out = W.V.
// 4-stage cp.async ring, smem rows padded to 80B (conflict-free ldmatrix).
// ===========================================================================
#define LDS_H    40                          // halves per smem row (32 + 8 pad)
#define TILE_B   (128 * LDS_H * 2)           // 10240 per operand tile
#define STG_B    (2 * TILE_B)                // 20480 per stage
#define NSTAGE   4
#define GEMM_SMEM (NSTAGE * STG_B)           // 81920 -> 2 CTAs/SM

template <int MODE>
__global__ void __launch_bounds__(128, 2) gemm_hmma(float* __restrict__ Dbase)
{
    constexpr int  KT  = (MODE == 0) ? KD : SEQ;
    constexpr int  LDA = (MODE == 0) ? KD : SEQ;
    constexpr int  LDB = (MODE == 0) ? KD : SEQ;
    constexpr long long ABS = (MODE == 0) ? (long long)SEQ * KD : (long long)SEQ * SEQ;
    constexpr long long BBS = (MODE == 0) ? (long long)SEQ * KD : (long long)HID * SEQ;
    constexpr int  LDD = (MODE == 0) ? SEQ : HID;
    constexpr long long DBS = (long long)SEQ * LDD;
    constexpr int  NC  = KT / 32;

    extern __shared__ __align__(256) char smem[];
    const uint32_t sb = smem_u32(smem);

    const int tid  = threadIdx.x;            // 128
    const int warp = tid >> 5;               // 0..3
    const int lane = tid & 31;
    const int wm   = warp & 1;               // 2 warps along M (64 rows each)
    const int wn   = warp >> 1;              // 2 warps along N (64 cols each)
    const int m0 = blockIdx.x * 128;
    const int n0 = blockIdx.y * 128;
    const int bz = blockIdx.z;

    const __half* A = ((MODE == 0) ? g_qf : g_wh) + (long long)bz * ABS + (long long)m0 * LDA;
    const __half* B = ((MODE == 0) ? g_kf : g_vt) + (long long)bz * BBS + (long long)n0 * LDB;

    const int lr = lane & 15;
    const int lc = lane >> 4;

    auto load_chunk = [&](int st, int kc) {
        const uint32_t abase = sb + st * STG_B;
        const uint32_t bbase = abase + TILE_B;
        const int k0 = kc * 32;
#pragma unroll
        for (int i = 0; i < 4; i++) {          // A: 128 rows x 4 segs / 128 thr
            const int idx = tid + i * 128;
            const int row = idx >> 2;
            const int seg = idx & 3;
            cp16(abase + (uint32_t)(row * (LDS_H * 2) + seg * 16),
                 A + (long long)row * LDA + k0 + seg * 8);
        }
#pragma unroll
        for (int i = 0; i < 4; i++) {          // B: 128 rows x 4 segs / 128 thr
            const int idx = tid + i * 128;
            const int row = idx >> 2;
            const int seg = idx & 3;
            cp16(bbase + (uint32_t)(row * (LDS_H * 2) + seg * 16),
                 B + (long long)row * LDB + k0 + seg * 8);
        }
        cp_commit();
    };

    float acc[4][8][4];
#pragma unroll
    for (int mt = 0; mt < 4; mt++)
#pragma unroll
        for (int nt = 0; nt < 8; nt++)
#pragma unroll
            for (int e = 0; e < 4; e++)
                acc[mt][nt][e] = 0.0f;

    load_chunk(0, 0);
    load_chunk(1, 1);
    load_chunk(2, 2);

#pragma unroll 1
    for (int c = 0; c < NC; c++) {
        if (c + NSTAGE - 1 < NC) cp_wait<NSTAGE - 2>(); else cp_wait<0>();
        __syncthreads();
        if (c + NSTAGE - 1 < NC)
            load_chunk((c + NSTAGE - 1) % NSTAGE, c + NSTAGE - 1);

        const uint32_t ab = sb + (c % NSTAGE) * STG_B;
        const uint32_t bb = ab + TILE_B;
#pragma unroll
        for (int ks = 0; ks < 2; ks++) {
            const uint32_t kofs = (uint32_t)((ks * 16 + lc * 8) * 2);
            uint32_t af[4][4];
            uint32_t bf[4][4];
#pragma unroll
            for (int mt = 0; mt < 4; mt++)
                LDSM4(af[mt], ab + (uint32_t)((wm * 64 + mt * 16 + lr) * (LDS_H * 2)) + kofs);
#pragma unroll
            for (int g = 0; g < 4; g++)
                LDSM4(bf[g], bb + (uint32_t)((wn * 64 + g * 16 + lr) * (LDS_H * 2)) + kofs);
#pragma unroll
            for (int mt = 0; mt < 4; mt++)
#pragma unroll
                for (int g = 0; g < 4; g++) {
                    MMA16816(acc[mt][2 * g],     af[mt][0], af[mt][1], af[mt][2], af[mt][3],
                             bf[g][0], bf[g][2]);
                    MMA16816(acc[mt][2 * g + 1], af[mt][0], af[mt][1], af[mt][2], af[mt][3],
                             bf[g][1], bf[g][3]);
                }
        }
    }

    // Epilogue: fused scale+bias (MODE 0), direct float2 stores
    float* D = Dbase + (long long)bz * DBS;
    const int tr = lane >> 2;
    const int tc = (lane & 3) * 2;
    const int mbase = m0 + wm * 64;
    const int nbase = n0 + wn * 64;
#pragma unroll
    for (int mt = 0; mt < 4; mt++)
#pragma unroll
        for (int nt = 0; nt < 8; nt++) {
            float v0 = acc[mt][nt][0], v1 = acc[mt][nt][1];
            float v2 = acc[mt][nt][2], v3 = acc[mt][nt][3];
            if (MODE == 0) {
                const float s = 1.0f / 513.0f;
                v0 = v0 * s + 1.0f;
                v1 = v1 * s + 1.0f;
                v2 = v2 * s + 1.0f;
                v3 = v3 * s + 1.0f;
            }
            const int row = mbase + mt * 16 + tr;
            const int col = nbase + nt * 8 + tc;
            *(float2*)(D + (long long)row * LDD + col)       = make_float2(v0, v1);
            *(float2*)(D + (long long)(row + 8) * LDD + col) = make_float2(v2, v3);
        }
}

// ===========================================================================
// Kernel 4: row softmax over 2048 fp32 (in place) + fp16 copy into g_wh
// ===========================================================================
__global__ void softmax_kernel(float* __restrict__ W)
{
    __shared__ float smax[8];
    __shared__ float ssum[8];
    const size_t row = blockIdx.x;
    float*  p  = W    + row * SEQ;
    __half* ph = g_wh + row * SEQ;
    const int t = threadIdx.x;

    float v[8];
    float m = -1e30f;
#pragma unroll
    for (int i = 0; i < 8; i++) {
        v[i] = p[t + 256 * i];
        m = fmaxf(m, v[i]);
    }
#pragma unroll
    for (int o = 16; o; o >>= 1) m = fmaxf(m, __shfl_xor_sync(0xffffffffu, m, o));
    if ((t & 31) == 0) smax[t >> 5] = m;
    __syncthreads();
    m = smax[0];
#pragma unroll
    for (int i = 1; i < 8; i++) m = fmaxf(m, smax[i]);

    float s = 0.0f;
#pragma unroll
    for (int i = 0; i < 8; i++) {
        v[i] = __expf(v[i] - m);
        s += v[i];
    }
#pragma unroll
    for (int o = 16; o; o >>= 1) s += __shfl_xor_sync(0xffffffffu, s, o);
    if ((t & 31) == 0) ssum[t >> 5] = s;
    __syncthreads();
    s = ssum[0];
#pragma unroll
    for (int i = 1; i < 8; i++) s += ssum[i];
    const float inv = 1.0f / s;

#pragma unroll
    for (int i = 0; i < 8; i++) {
        const float w = v[i] * inv;
        p[t + 256 * i]  = w;
        ph[t + 256 * i] = __float2half(w);
    }
}

// ===========================================================================
// Launch: out = [output (B*S*H fp32) | weights (B*S*S fp32)]
// ===========================================================================
extern "C" void kernel_launch(void* const* d_in, const int* in_sizes, int n_in,
                              void* d_out, int out_size)
{
    const float* Q = (const float*)d_in[0];
    const float* K = (const float*)d_in[1];
    const float* V = (const float*)d_in[2];
    float* out     = (float*)d_out;
    float* weights = out + (size_t)BATCH * SEQ * HID;

    cudaFuncSetAttribute(gemm_hmma<0>, cudaFuncAttributeMaxDynamicSharedMemorySize, GEMM_SMEM);
    cudaFuncSetAttribute(gemm_hmma<1>, cudaFuncAttributeMaxDynamicSharedMemorySize, GEMM_SMEM);

    // 0) twiddle table (once per launch; tiny)
    twiddle_init_kernel<<<3, 256>>>();

    // 1) phase features for Q and K (two rows per block)
    fft_phase_kernel<<<ROWS, 256>>>(Q, K);

    // 2) V -> fp16 transposed [b][h][j]
    {
        dim3 grid(HID / 32, SEQ / 32, BATCH);
        vtrans_kernel<<<grid, dim3(32, 8)>>>(V);
    }

    // 3) scores = QF . KF^T / 513 + 1  (fp32, into weights region)
    {
        dim3 grid(SEQ / 128, SEQ / 128, BATCH);
        gemm_hmma<0><<<grid, 128, GEMM_SMEM>>>(weights);
    }

    // 4) softmax rows in place (+ fp16 copy)
    softmax_kernel<<<ROWS, 256>>>(weights);

    // 5) output = weights @ V
    {
        dim3 grid(SEQ / 128, HID / 128, BATCH);
        gemm_hmma<1><<<grid, 128, GEMM_SMEM>>>(out);
    }
}

// round 10
// speedup vs baseline: 1.6386x; 1.0483x over previous
#include <cuda_runtime.h>
#include <cuda_fp16.h>
#include <stdint.h>

// Problem constants
#define BATCH 4
#define SEQ   2048
#define HID   1024
#define NFREQ 513           // H/2 + 1
#define KD    1088          // 2*NFREQ (=1026) padded to multiple of 32
#define ROWS  (BATCH * SEQ) // 8192

// Scratch (static __device__ — no allocations allowed)
__device__ __align__(256) __half g_qf[(size_t)ROWS * KD];         // Q phase features
__device__ __align__(256) __half g_kf[(size_t)ROWS * KD];         // K phase features
__device__ __align__(256) __half g_wh[(size_t)ROWS * SEQ];        // fp16 softmax weights
__device__ __align__(256) __half g_vt[(size_t)BATCH * HID * SEQ]; // V^T [b][h][j] fp16
__device__ float2 g_tw[768];                                      // W_1024^t, t=0..767

// ===========================================================================
// PTX helpers
// ===========================================================================
__device__ __forceinline__ uint32_t smem_u32(const void* p) {
    uint32_t a;
    asm("{ .reg .u64 t; cvta.to.shared.u64 t, %1; cvt.u32.u64 %0, t; }"
        : "=r"(a) : "l"(p));
    return a;
}
__device__ __forceinline__ uint32_t elect_one() {
    uint32_t p;
    asm volatile(
        "{\n\t.reg .pred p;\n\telect.sync _|p, 0xFFFFFFFF;\n\t"
        "selp.b32 %0, 1, 0, p;\n\t}" : "=r"(p));
    return p;
}
__device__ __forceinline__ void cp16(uint32_t dst, const void* src) {
    asm volatile("cp.async.cg.shared.global [%0], [%1], 16;" :: "r"(dst), "l"(src));
}

#define MBARRIER_INIT(addr, cnt) \
    asm volatile("mbarrier.init.shared.b64 [%0], %1;" :: "r"((uint32_t)(addr)), "r"((uint32_t)(cnt)) : "memory")
#define MBARRIER_ARRIVE(addr) \
    asm volatile("mbarrier.arrive.shared.b64 _, [%0];" :: "r"((uint32_t)(addr)) : "memory")
#define CPASYNC_MBAR_ARRIVE_NOINC(addr) \
    asm volatile("cp.async.mbarrier.arrive.noinc.shared.b64 [%0];" :: "r"((uint32_t)(addr)) : "memory")

#define MBARRIER_WAIT_PARITY(mbar_smem_addr, phase_parity) do { \
    uint32_t _mbar = (uint32_t)(mbar_smem_addr); \
    uint32_t _parity = (uint32_t)(phase_parity); \
    uint32_t _done; \
    asm volatile( \
        "{\n\t.reg .pred p;\n\t" \
        "mbarrier.try_wait.parity.acquire.cta.shared::cta.b64 p, [%1], %2;\n\t" \
        "selp.b32 %0, 1, 0, p;\n\t}" \
        : "=r"(_done) : "r"(_mbar), "r"(_parity) : "memory"); \
    if (!_done) { \
        asm volatile( \
            "{\n\t.reg .pred P1;\n\t" \
            "WAIT_LOOP_%=:\n\t" \
            "mbarrier.try_wait.parity.acquire.cta.shared::cta.b64 P1, [%0], %1, 0x989680;\n\t" \
            "@P1 bra.uni WAIT_DONE_%=;\n\t" \
            "bra.uni WAIT_LOOP_%=;\n\t" \
            "WAIT_DONE_%=:\n\t}" \
            :: "r"(_mbar), "r"(_parity) : "memory"); \
    } \
} while (0)

#define LDSM4(r, a)                                                          \
    asm volatile("ldmatrix.sync.aligned.m8n8.x4.shared.b16 {%0,%1,%2,%3}, [%4];" \
                 : "=r"((r)[0]), "=r"((r)[1]), "=r"((r)[2]), "=r"((r)[3])    \
                 : "r"(a))

#define MMA16816(d, a0, a1, a2, a3, b0, b1)                                  \
    asm volatile(                                                            \
        "mma.sync.aligned.m16n8k16.row.col.f32.f16.f16.f32 "                 \
        "{%0,%1,%2,%3}, {%4,%5,%6,%7}, {%8,%9}, {%0,%1,%2,%3};"              \
        : "+f"((d)[0]), "+f"((d)[1]), "+f"((d)[2]), "+f"((d)[3])             \
        : "r"(a0), "r"(a1), "r"(a2), "r"(a3), "r"(b0), "r"(b1))

// ===========================================================================
// Kernel 0: one-time twiddle table W_1024^t = exp(-2*pi*i*t/1024), t<768
// ===========================================================================
__global__ void twiddle_init_kernel()
{
    const int t = blockIdx.x * 256 + threadIdx.x;
    if (t < 768) {
        float s, c;
        sincosf(-6.283185307179586f * (float)t * (1.0f / 1024.0f), &s, &c);
        g_tw[t] = make_float2(c, s);
    }
}

// ===========================================================================
// Kernel 1: two real rows per block packed into ONE complex FFT-1024
// (radix-4 DIF, 5 stages), untangle at readout.
// ===========================================================================
#define FPAD(i) ((i) + ((i) >> 4))

__global__ void fft_phase_kernel(const float* __restrict__ Q,
                                 const float* __restrict__ K)
{
    __shared__ float2 sd[1024 + 64];
    __shared__ float2 stw[768];

    const int t = threadIdx.x;                 // 256 threads
    const bool isK = blockIdx.x >= (ROWS / 2);
    const int pr = blockIdx.x & (ROWS / 2 - 1);
    const float* srcA = (isK ? K : Q) + (size_t)(2 * pr) * HID;
    const float* srcB = srcA + HID;
    __half* dstA = (isK ? g_kf : g_qf) + (size_t)(2 * pr) * KD;
    __half* dstB = dstA + KD;

#pragma unroll
    for (int i = t; i < 768; i += 256)
        stw[i] = g_tw[i];

    {
        const float4 fa = ((const float4*)srcA)[t];
        const float4 fb = ((const float4*)srcB)[t];
        sd[FPAD(4 * t + 0)] = make_float2(fa.x, fb.x);
        sd[FPAD(4 * t + 1)] = make_float2(fa.y, fb.y);
        sd[FPAD(4 * t + 2)] = make_float2(fa.z, fb.z);
        sd[FPAD(4 * t + 3)] = make_float2(fa.w, fb.w);
    }
    __syncthreads();

#pragma unroll
    for (int st = 0; st < 5; st++) {
        const int qlog = 8 - 2 * st;
        const int q    = 1 << qlog;
        const int j    = t & (q - 1);
        const int sub  = t >> qlog;
        const int base = (sub << (qlog + 2)) | j;
        const int tw   = j << (2 * st);

        const float2 x0 = sd[FPAD(base)];
        const float2 x1 = sd[FPAD(base + q)];
        const float2 x2 = sd[FPAD(base + 2 * q)];
        const float2 x3 = sd[FPAD(base + 3 * q)];

        const float b0r = x0.x + x2.x, b0i = x0.y + x2.y;
        const float b1r = x1.x + x3.x, b1i = x1.y + x3.y;
        const float b2r = x0.x - x2.x, b2i = x0.y - x2.y;
        const float b3r = x1.x - x3.x, b3i = x1.y - x3.y;

        float y0r = b0r + b1r, y0i = b0i + b1i;
        float y1r = b2r + b3i, y1i = b2i - b3r;
        float y2r = b0r - b1r, y2i = b0i - b1i;
        float y3r = b2r - b3i, y3i = b2i + b3r;

        if (st < 4) {
            const float2 w1 = stw[tw];
            const float2 w2 = stw[2 * tw];
            const float2 w3 = stw[3 * tw];
            float r;
            r   = y1r * w1.x - y1i * w1.y;
            y1i = y1r * w1.y + y1i * w1.x;  y1r = r;
            r   = y2r * w2.x - y2i * w2.y;
            y2i = y2r * w2.y + y2i * w2.x;  y2r = r;
            r   = y3r * w3.x - y3i * w3.y;
            y3i = y3r * w3.y + y3i * w3.x;  y3r = r;
        }

        sd[FPAD(base)]         = make_float2(y0r, y0i);
        sd[FPAD(base + q)]     = make_float2(y1r, y1i);
        sd[FPAD(base + 2 * q)] = make_float2(y2r, y2i);
        sd[FPAD(base + 3 * q)] = make_float2(y3r, y3i);
        __syncthreads();
    }

    for (int k = t; k < NFREQ; k += 256) {
        const int kb  = (1024 - k) & 1023;
        const int ra  = __brev((unsigned)k)  >> 22;
        const int rb  = __brev((unsigned)kb) >> 22;
        const int pa  = ((ra & 0x155) << 1) | ((ra & 0x2AA) >> 1);
        const int pb  = ((rb & 0x155) << 1) | ((rb & 0x2AA) >> 1);
        const float2 za = sd[FPAD(pa)];
        const float2 zb = sd[FPAD(pb)];

        const float ar = za.x + zb.x;
        const float ai = za.y - zb.y;
        const float br = za.y + zb.y;
        const float bi = zb.x - za.x;

        {
            const float m2 = ar * ar + ai * ai;
            float cc = 1.0f, ss = 0.0f;
            if (m2 > 0.0f) {
                const float inv = rsqrtf(m2);
                cc = ar * inv;
                ss = ai * inv;
            }
            dstA[k]         = __float2half(cc);
            dstA[NFREQ + k] = __float2half(ss);
        }
        {
            const float m2 = br * br + bi * bi;
            float cc = 1.0f, ss = 0.0f;
            if (m2 > 0.0f) {
                const float inv = rsqrtf(m2);
                cc = br * inv;
                ss = bi * inv;
            }
            dstB[k]         = __float2half(cc);
            dstB[NFREQ + k] = __float2half(ss);
        }
    }
    for (int k = 2 * NFREQ + t; k < KD; k += 256) {
        dstA[k] = __float2half(0.0f);
        dstB[k] = __float2half(0.0f);
    }
}

// ===========================================================================
// Kernel 2: V [b][j][h] fp32 -> g_vt [b][h][j] fp16 (32x32 smem transpose)
// ===========================================================================
__global__ void vtrans_kernel(const float* __restrict__ V)
{
    __shared__ float s[32][33];
    const int b  = blockIdx.z;
    const int h0 = blockIdx.x * 32;
    const int j0 = blockIdx.y * 32;
    const int tx = threadIdx.x, ty = threadIdx.y;   // 32 x 8

    const float* src = V + ((size_t)b * SEQ + j0) * HID + h0;
#pragma unroll
    for (int r = 0; r < 32; r += 8)
        s[ty + r][tx] = src[(size_t)(ty + r) * HID + tx];
    __syncthreads();

    __half* dst = g_vt + ((size_t)b * HID + h0) * SEQ + j0;
#pragma unroll
    for (int r = 0; r < 32; r += 8)
        dst[(size_t)(ty + r) * SEQ + tx] = __float2half(s[tx][ty + r]);
}

// ===========================================================================
// Kernel 3/5: WARP-SPECIALIZED pipelined HMMA NT GEMM.
// 128x128x32 CTA tile; warps 0-3 = consumers (64x64 each, 2x2), warps 4-5 =
// producers (warp4 -> A tile, warp5 -> B tile). 4-stage ring with per-stage
// full/empty mbarriers; NO __syncthreads / cp_wait in the main loop.
// MODE 0: scores = QF.KF^T/513 + 1.  MODE 1: out = W.V.
// ===========================================================================
#define LDS_H    40                          // halves per smem row (32 + 8 pad)
#define TILE_B   (128 * LDS_H * 2)           // 10240 per operand tile
#define STG_B    (2 * TILE_B)                // 20480 per stage
#define NSTAGE   4
#define CTRL_B   1024
#define GEMM_SMEM (CTRL_B + NSTAGE * STG_B)  // 82944 -> 2 CTAs/SM

template <int MODE>
__global__ void __launch_bounds__(192, 2) gemm_hmma(float* __restrict__ Dbase)
{
    constexpr int  KT  = (MODE == 0) ? KD : SEQ;
    constexpr int  LDA = (MODE == 0) ? KD : SEQ;
    constexpr int  LDB = (MODE == 0) ? KD : SEQ;
    constexpr long long ABS = (MODE == 0) ? (long long)SEQ * KD : (long long)SEQ * SEQ;
    constexpr long long BBS = (MODE == 0) ? (long long)SEQ * KD : (long long)HID * SEQ;
    constexpr int  LDD = (MODE == 0) ? SEQ : HID;
    constexpr long long DBS = (long long)SEQ * LDD;
    constexpr int  NC  = KT / 32;

    extern __shared__ __align__(256) char smem[];
    const uint32_t sb = smem_u32(smem);
    // mbarriers: full[s] = sb + 16s, empty[s] = sb + 16s + 8

    const int tid  = threadIdx.x;            // 192
    const int warp = tid >> 5;               // 0..5
    const int lane = tid & 31;
    const int m0 = blockIdx.x * 128;
    const int n0 = blockIdx.y * 128;
    const int bz = blockIdx.z;

    const __half* A = ((MODE == 0) ? g_qf : g_wh) + (long long)bz * ABS + (long long)m0 * LDA;
    const __half* B = ((MODE == 0) ? g_kf : g_vt) + (long long)bz * BBS + (long long)n0 * LDB;

    if (tid == 0) {
#pragma unroll
        for (int s = 0; s < NSTAGE; s++) {
            MBARRIER_INIT(sb + 16 * s,     64); // full: 64 producer lanes
            MBARRIER_INIT(sb + 16 * s + 8, 4);  // empty: 4 consumer warps
        }
    }
    __syncthreads();

    if (warp >= 4) {
        // ------------------- producer: warp4 -> A, warp5 -> B -------------
        const __half* src = (warp == 4) ? A : B;
        const int     ld  = (warp == 4) ? LDA : LDB;
        const uint32_t tb0 = sb + CTRL_B + ((warp == 4) ? 0u : (uint32_t)TILE_B);
        int pph = 1;
#pragma unroll 1
        for (int c = 0; c < NC; c++) {
            const int st = c & (NSTAGE - 1);
            MBARRIER_WAIT_PARITY(sb + 16 * st + 8, pph);
            const uint32_t tb = tb0 + st * STG_B;
            const int k0 = c * 32;
#pragma unroll
            for (int j = 0; j < 16; j++) {          // 512 cp16 per tile / 32 lanes
                const int idx = lane + j * 32;
                const int row = idx >> 2;
                const int seg = idx & 3;
                cp16(tb + (uint32_t)(row * (LDS_H * 2) + seg * 16),
                     src + (long long)row * ld + k0 + seg * 8);
            }
            CPASYNC_MBAR_ARRIVE_NOINC(sb + 16 * st);
            if (st == NSTAGE - 1) pph ^= 1;
        }
    } else {
        // ------------------- consumer: 2x2 warps, 64x64 tiles --------------
        const int wm = warp & 1;
        const int wn = warp >> 1;
        const int lr = lane & 15;
        const int lc = lane >> 4;

        float acc[4][8][4];
#pragma unroll
        for (int mt = 0; mt < 4; mt++)
#pragma unroll
            for (int nt = 0; nt < 8; nt++)
#pragma unroll
                for (int e = 0; e < 4; e++)
                    acc[mt][nt][e] = 0.0f;

        int cph = 0;
#pragma unroll 1
        for (int c = 0; c < NC; c++) {
            const int st = c & (NSTAGE - 1);
            MBARRIER_WAIT_PARITY(sb + 16 * st, cph);
            const uint32_t ab = sb + CTRL_B + st * STG_B;
            const uint32_t bb = ab + TILE_B;
#pragma unroll
            for (int ks = 0; ks < 2; ks++) {
                const uint32_t kofs = (uint32_t)((ks * 16 + lc * 8) * 2);
                uint32_t af[4][4];
                uint32_t bf[4][4];
#pragma unroll
                for (int mt = 0; mt < 4; mt++)
                    LDSM4(af[mt], ab + (uint32_t)((wm * 64 + mt * 16 + lr) * (LDS_H * 2)) + kofs);
#pragma unroll
                for (int g = 0; g < 4; g++)
                    LDSM4(bf[g], bb + (uint32_t)((wn * 64 + g * 16 + lr) * (LDS_H * 2)) + kofs);
#pragma unroll
                for (int mt = 0; mt < 4; mt++)
#pragma unroll
                    for (int g = 0; g < 4; g++) {
                        MMA16816(acc[mt][2 * g],     af[mt][0], af[mt][1], af[mt][2], af[mt][3],
                                 bf[g][0], bf[g][2]);
                        MMA16816(acc[mt][2 * g + 1], af[mt][0], af[mt][1], af[mt][2], af[mt][3],
                                 bf[g][1], bf[g][3]);
                    }
            }
            __syncwarp();
            if (elect_one())
                MBARRIER_ARRIVE(sb + 16 * st + 8);
            if (st == NSTAGE - 1) cph ^= 1;
        }

        // Epilogue: fused scale+bias (MODE 0), direct float2 stores
        float* D = Dbase + (long long)bz * DBS;
        const int tr = lane >> 2;
        const int tc = (lane & 3) * 2;
        const int mbase = m0 + wm * 64;
        const int nbase = n0 + wn * 64;
#pragma unroll
        for (int mt = 0; mt < 4; mt++)
#pragma unroll
            for (int nt = 0; nt < 8; nt++) {
                float v0 = acc[mt][nt][0], v1 = acc[mt][nt][1];
                float v2 = acc[mt][nt][2], v3 = acc[mt][nt][3];
                if (MODE == 0) {
                    const float s = 1.0f / 513.0f;
                    v0 = v0 * s + 1.0f;
                    v1 = v1 * s + 1.0f;
                    v2 = v2 * s + 1.0f;
                    v3 = v3 * s + 1.0f;
                }
                const int row = mbase + mt * 16 + tr;
                const int col = nbase + nt * 8 + tc;
                *(float2*)(D + (long long)row * LDD + col)       = make_float2(v0, v1);
                *(float2*)(D + (long long)(row + 8) * LDD + col) = make_float2(v2, v3);
            }
    }
}

// ===========================================================================
// Kernel 4: row softmax over 2048 fp32 (in place) + fp16 copy into g_wh
// ===========================================================================
__global__ void softmax_kernel(float* __restrict__ W)
{
    __shared__ float smax[8];
    __shared__ float ssum[8];
    const size_t row = blockIdx.x;
    float*  p  = W    + row * SEQ;
    __half* ph = g_wh + row * SEQ;
    const int t = threadIdx.x;

    float v[8];
    float m = -1e30f;
#pragma unroll
    for (int i = 0; i < 8; i++) {
        v[i] = p[t + 256 * i];
        m = fmaxf(m, v[i]);
    }
#pragma unroll
    for (int o = 16; o; o >>= 1) m = fmaxf(m, __shfl_xor_sync(0xffffffffu, m, o));
    if ((t & 31) == 0) smax[t >> 5] = m;
    __syncthreads();
    m = smax[0];
#pragma unroll
    for (int i = 1; i < 8; i++) m = fmaxf(m, smax[i]);

    float s = 0.0f;
#pragma unroll
    for (int i = 0; i < 8; i++) {
        v[i] = __expf(v[i] - m);
        s += v[i];
    }
#pragma unroll
    for (int o = 16; o; o >>= 1) s += __shfl_xor_sync(0xffffffffu, s, o);
    if ((t & 31) == 0) ssum[t >> 5] = s;
    __syncthreads();
    s = ssum[0];
#pragma unroll
    for (int i = 1; i < 8; i++) s += ssum[i];
    const float inv = 1.0f / s;

#pragma unroll
    for (int i = 0; i < 8; i++) {
        const float w = v[i] * inv;
        p[t + 256 * i]  = w;
        ph[t + 256 * i] = __float2half(w);
    }
}

// ===========================================================================
// Launch: out = [output (B*S*H fp32) | weights (B*S*S fp32)]
// ===========================================================================
extern "C" void kernel_launch(void* const* d_in, const int* in_sizes, int n_in,
                              void* d_out, int out_size)
{
    const float* Q = (const float*)d_in[0];
    const float* K = (const float*)d_in[1];
    const float* V = (const float*)d_in[2];
    float* out     = (float*)d_out;
    float* weights = out + (size_t)BATCH * SEQ * HID;

    cudaFuncSetAttribute(gemm_hmma<0>, cudaFuncAttributeMaxDynamicSharedMemorySize, GEMM_SMEM);
    cudaFuncSetAttribute(gemm_hmma<1>, cudaFuncAttributeMaxDynamicSharedMemorySize, GEMM_SMEM);

    // 0) twiddle table (once per launch; tiny)
    twiddle_init_kernel<<<3, 256>>>();

    // 1) phase features for Q and K (two rows per block)
    fft_phase_kernel<<<ROWS, 256>>>(Q, K);

    // 2) V -> fp16 transposed [b][h][j]
    {
        dim3 grid(HID / 32, SEQ / 32, BATCH);
        vtrans_kernel<<<grid, dim3(32, 8)>>>(V);
    }

    // 3) scores = QF . KF^T / 513 + 1  (fp32, into weights region)
    {
        dim3 grid(SEQ / 128, SEQ / 128, BATCH);
        gemm_hmma<0><<<grid, 192, GEMM_SMEM>>>(weights);
    }

    // 4) softmax rows in place (+ fp16 copy)
    softmax_kernel<<<ROWS, 256>>>(weights);

    // 5) output = weights @ V
    {
        dim3 grid(SEQ / 128, HID / 128, BATCH);
        gemm_hmma<1><<<grid, 192, GEMM_SMEM>>>(out);
    }
}

// round 11
// speedup vs baseline: 1.6994x; 1.0371x over previous
#include <cuda_runtime.h>
#include <cuda_fp16.h>
#include <stdint.h>

// Problem constants
#define BATCH 4
#define SEQ   2048
#define HID   1024
#define NFREQ 513           // H/2 + 1
#define KD    1088          // 2*NFREQ (=1026) padded to multiple of 64
#define ROWS  (BATCH * SEQ) // 8192

// Scratch (static __device__ — no allocations allowed)
__device__ __align__(256) __half g_qf[(size_t)ROWS * KD];         // Q phase features
__device__ __align__(256) __half g_kf[(size_t)ROWS * KD];         // K phase features
__device__ __align__(256) __half g_wh[(size_t)ROWS * SEQ];        // fp16 exp / weights
__device__ __align__(256) __half g_vt[(size_t)BATCH * HID * SEQ]; // V^T [b][h][j] fp16
__device__ float2 g_tw[768];                                      // W_1024^t, t=0..767

// ===========================================================================
// PTX helpers
// ===========================================================================
__device__ __forceinline__ uint32_t smem_u32(const void* p) {
    uint32_t a;
    asm("{ .reg .u64 t; cvta.to.shared.u64 t, %1; cvt.u32.u64 %0, t; }"
        : "=r"(a) : "l"(p));
    return a;
}
__device__ __forceinline__ uint32_t elect_one() {
    uint32_t p;
    asm volatile(
        "{\n\t.reg .pred p;\n\telect.sync _|p, 0xFFFFFFFF;\n\t"
        "selp.b32 %0, 1, 0, p;\n\t}" : "=r"(p));
    return p;
}
__device__ __forceinline__ void cp16(uint32_t dst, const void* src) {
    asm volatile("cp.async.cg.shared.global [%0], [%1], 16;" :: "r"(dst), "l"(src));
}

#define MBARRIER_INIT(addr, cnt) \
    asm volatile("mbarrier.init.shared.b64 [%0], %1;" :: "r"((uint32_t)(addr)), "r"((uint32_t)(cnt)) : "memory")
#define MBARRIER_ARRIVE(addr) \
    asm volatile("mbarrier.arrive.shared.b64 _, [%0];" :: "r"((uint32_t)(addr)) : "memory")
#define CPASYNC_MBAR_ARRIVE_NOINC(addr) \
    asm volatile("cp.async.mbarrier.arrive.noinc.shared.b64 [%0];" :: "r"((uint32_t)(addr)) : "memory")

#define MBARRIER_WAIT_PARITY(mbar_smem_addr, phase_parity) do { \
    uint32_t _mbar = (uint32_t)(mbar_smem_addr); \
    uint32_t _parity = (uint32_t)(phase_parity); \
    uint32_t _done; \
    asm volatile( \
        "{\n\t.reg .pred p;\n\t" \
        "mbarrier.try_wait.parity.acquire.cta.shared::cta.b64 p, [%1], %2;\n\t" \
        "selp.b32 %0, 1, 0, p;\n\t}" \
        : "=r"(_done) : "r"(_mbar), "r"(_parity) : "memory"); \
    if (!_done) { \
        asm volatile( \
            "{\n\t.reg .pred P1;\n\t" \
            "WAIT_LOOP_%=:\n\t" \
            "mbarrier.try_wait.parity.acquire.cta.shared::cta.b64 P1, [%0], %1, 0x989680;\n\t" \
            "@P1 bra.uni WAIT_DONE_%=;\n\t" \
            "bra.uni WAIT_LOOP_%=;\n\t" \
            "WAIT_DONE_%=:\n\t}" \
            :: "r"(_mbar), "r"(_parity) : "memory"); \
    } \
} while (0)

#define LDSM4(r, a)                                                          \
    asm volatile("ldmatrix.sync.aligned.m8n8.x4.shared.b16 {%0,%1,%2,%3}, [%4];" \
                 : "=r"((r)[0]), "=r"((r)[1]), "=r"((r)[2]), "=r"((r)[3])    \
                 : "r"(a))

#define MMA16816(d, a0, a1, a2, a3, b0, b1)                                  \
    asm volatile(                                                            \
        "mma.sync.aligned.m16n8k16.row.col.f32.f16.f16.f32 "                 \
        "{%0,%1,%2,%3}, {%4,%5,%6,%7}, {%8,%9}, {%0,%1,%2,%3};"              \
        : "+f"((d)[0]), "+f"((d)[1]), "+f"((d)[2]), "+f"((d)[3])             \
        : "r"(a0), "r"(a1), "r"(a2), "r"(a3), "r"(b0), "r"(b1))

// 128B-row XOR swizzle: rows 0..127, bits[6:4] ^= row&7
#define SWZ(o) ((o) ^ ((((o) >> 7) & 7) << 4))

// ===========================================================================
// Kernel 0: one-time twiddle table W_1024^t = exp(-2*pi*i*t/1024), t<768
// ===========================================================================
__global__ void twiddle_init_kernel()
{
    const int t = blockIdx.x * 256 + threadIdx.x;
    if (t < 768) {
        float s, c;
        sincosf(-6.283185307179586f * (float)t * (1.0f / 1024.0f), &s, &c);
        g_tw[t] = make_float2(c, s);
    }
}

// ===========================================================================
// Kernel 1: two real rows per block packed into ONE complex FFT-1024
// (radix-4 DIF, 5 stages), untangle at readout.
// ===========================================================================
#define FPAD(i) ((i) + ((i) >> 4))

__global__ void fft_phase_kernel(const float* __restrict__ Q,
                                 const float* __restrict__ K)
{
    __shared__ float2 sd[1024 + 64];
    __shared__ float2 stw[768];

    const int t = threadIdx.x;                 // 256 threads
    const bool isK = blockIdx.x >= (ROWS / 2);
    const int pr = blockIdx.x & (ROWS / 2 - 1);
    const float* srcA = (isK ? K : Q) + (size_t)(2 * pr) * HID;
    const float* srcB = srcA + HID;
    __half* dstA = (isK ? g_kf : g_qf) + (size_t)(2 * pr) * KD;
    __half* dstB = dstA + KD;

#pragma unroll
    for (int i = t; i < 768; i += 256)
        stw[i] = g_tw[i];

    {
        const float4 fa = ((const float4*)srcA)[t];
        const float4 fb = ((const float4*)srcB)[t];
        sd[FPAD(4 * t + 0)] = make_float2(fa.x, fb.x);
        sd[FPAD(4 * t + 1)] = make_float2(fa.y, fb.y);
        sd[FPAD(4 * t + 2)] = make_float2(fa.z, fb.z);
        sd[FPAD(4 * t + 3)] = make_float2(fa.w, fb.w);
    }
    __syncthreads();

#pragma unroll
    for (int st = 0; st < 5; st++) {
        const int qlog = 8 - 2 * st;
        const int q    = 1 << qlog;
        const int j    = t & (q - 1);
        const int sub  = t >> qlog;
        const int base = (sub << (qlog + 2)) | j;
        const int tw   = j << (2 * st);

        const float2 x0 = sd[FPAD(base)];
        const float2 x1 = sd[FPAD(base + q)];
        const float2 x2 = sd[FPAD(base + 2 * q)];
        const float2 x3 = sd[FPAD(base + 3 * q)];

        const float b0r = x0.x + x2.x, b0i = x0.y + x2.y;
        const float b1r = x1.x + x3.x, b1i = x1.y + x3.y;
        const float b2r = x0.x - x2.x, b2i = x0.y - x2.y;
        const float b3r = x1.x - x3.x, b3i = x1.y - x3.y;

        float y0r = b0r + b1r, y0i = b0i + b1i;
        float y1r = b2r + b3i, y1i = b2i - b3r;
        float y2r = b0r - b1r, y2i = b0i - b1i;
        float y3r = b2r - b3i, y3i = b2i + b3r;

        if (st < 4) {
            const float2 w1 = stw[tw];
            const float2 w2 = stw[2 * tw];
            const float2 w3 = stw[3 * tw];
            float r;
            r   = y1r * w1.x - y1i * w1.y;
            y1i = y1r * w1.y + y1i * w1.x;  y1r = r;
            r   = y2r * w2.x - y2i * w2.y;
            y2i = y2r * w2.y + y2i * w2.x;  y2r = r;
            r   = y3r * w3.x - y3i * w3.y;
            y3i = y3r * w3.y + y3i * w3.x;  y3r = r;
        }

        sd[FPAD(base)]         = make_float2(y0r, y0i);
        sd[FPAD(base + q)]     = make_float2(y1r, y1i);
        sd[FPAD(base + 2 * q)] = make_float2(y2r, y2i);
        sd[FPAD(base + 3 * q)] = make_float2(y3r, y3i);
        __syncthreads();
    }

    for (int k = t; k < NFREQ; k += 256) {
        const int kb  = (1024 - k) & 1023;
        const int ra  = __brev((unsigned)k)  >> 22;
        const int rb  = __brev((unsigned)kb) >> 22;
        const int pa  = ((ra & 0x155) << 1) | ((ra & 0x2AA) >> 1);
        const int pb  = ((rb & 0x155) << 1) | ((rb & 0x2AA) >> 1);
        const float2 za = sd[FPAD(pa)];
        const float2 zb = sd[FPAD(pb)];

        const float ar = za.x + zb.x;
        const float ai = za.y - zb.y;
        const float br = za.y + zb.y;
        const float bi = zb.x - za.x;

        {
            const float m2 = ar * ar + ai * ai;
            float cc = 1.0f, ss = 0.0f;
            if (m2 > 0.0f) {
                const float inv = rsqrtf(m2);
                cc = ar * inv;
                ss = ai * inv;
            }
            dstA[k]         = __float2half(cc);
            dstA[NFREQ + k] = __float2half(ss);
        }
        {
            const float m2 = br * br + bi * bi;
            float cc = 1.0f, ss = 0.0f;
            if (m2 > 0.0f) {
                const float inv = rsqrtf(m2);
                cc = br * inv;
                ss = bi * inv;
            }
            dstB[k]         = __float2half(cc);
            dstB[NFREQ + k] = __float2half(ss);
        }
    }
    for (int k = 2 * NFREQ + t; k < KD; k += 256) {
        dstA[k] = __float2half(0.0f);
        dstB[k] = __float2half(0.0f);
    }
}

// ===========================================================================
// Kernel 2: V [b][j][h] fp32 -> g_vt [b][h][j] fp16 (32x32 smem transpose)
// ===========================================================================
__global__ void vtrans_kernel(const float* __restrict__ V)
{
    __shared__ float s[32][33];
    const int b  = blockIdx.z;
    const int h0 = blockIdx.x * 32;
    const int j0 = blockIdx.y * 32;
    const int tx = threadIdx.x, ty = threadIdx.y;   // 32 x 8

    const float* src = V + ((size_t)b * SEQ + j0) * HID + h0;
#pragma unroll
    for (int r = 0; r < 32; r += 8)
        s[ty + r][tx] = src[(size_t)(ty + r) * HID + tx];
    __syncthreads();

    __half* dst = g_vt + ((size_t)b * HID + h0) * SEQ + j0;
#pragma unroll
    for (int r = 0; r < 32; r += 8)
        dst[(size_t)(ty + r) * SEQ + tx] = __float2half(s[tx][ty + r]);
}

// ===========================================================================
// Kernel 3/5: WARP-SPECIALIZED pipelined HMMA NT GEMM, BK=64 chunks.
// 128x128 CTA tile; warps 0-3 consumers (64x64, 2x2), warps 4-5 producers.
// 3-stage ring, 128B XOR-swizzled smem rows (no pad), mbarrier handoff.
// MODE 0: g_wh = fp16 exp(QF.KF^T/513 + 1).   MODE 1: out = W.V (fp32).
// ===========================================================================
#define TILE_B   (128 * 128)                 // 16384 B per operand tile
#define STG_B    (2 * TILE_B)                // 32768 per stage
#define NSTAGE   3
#define CTRL_B   1024
#define GEMM_SMEM (CTRL_B + NSTAGE * STG_B)  // 99328 -> 2 CTAs/SM

template <int MODE>
__global__ void __launch_bounds__(192, 2) gemm_hmma(float* __restrict__ Dbase)
{
    constexpr int  KT  = (MODE == 0) ? KD : SEQ;
    constexpr int  LDA = (MODE == 0) ? KD : SEQ;
    constexpr int  LDB = (MODE == 0) ? KD : SEQ;
    constexpr long long ABS = (MODE == 0) ? (long long)SEQ * KD : (long long)SEQ * SEQ;
    constexpr long long BBS = (MODE == 0) ? (long long)SEQ * KD : (long long)HID * SEQ;
    constexpr int  LDD = (MODE == 0) ? SEQ : HID;
    constexpr long long DBS = (long long)SEQ * LDD;
    constexpr int  NC  = KT / 64;

    extern __shared__ __align__(256) char smem[];
    const uint32_t sb = smem_u32(smem);
    // mbarriers: full[s] = sb + 16s, empty[s] = sb + 16s + 8

    const int tid  = threadIdx.x;            // 192
    const int warp = tid >> 5;               // 0..5
    const int lane = tid & 31;
    const int m0 = blockIdx.x * 128;
    const int n0 = blockIdx.y * 128;
    const int bz = blockIdx.z;

    const __half* A = ((MODE == 0) ? g_qf : g_wh) + (long long)bz * ABS + (long long)m0 * LDA;
    const __half* B = ((MODE == 0) ? g_kf : g_vt) + (long long)bz * BBS + (long long)n0 * LDB;

    if (tid == 0) {
#pragma unroll
        for (int s = 0; s < NSTAGE; s++) {
            MBARRIER_INIT(sb + 16 * s,     64); // full: 64 producer lanes
            MBARRIER_INIT(sb + 16 * s + 8, 4);  // empty: 4 consumer warps
        }
    }
    __syncthreads();

    if (warp >= 4) {
        // ------------------- producer: warp4 -> A, warp5 -> B -------------
        const __half* src = (warp == 4) ? A : B;
        const int     ld  = (warp == 4) ? LDA : LDB;
        const uint32_t tb0 = sb + CTRL_B + ((warp == 4) ? 0u : (uint32_t)TILE_B);
        int pph = 1;
#pragma unroll 1
        for (int c = 0; c < NC; c++) {
            const int st = (c % NSTAGE);
            MBARRIER_WAIT_PARITY(sb + 16 * st + 8, pph);
            const uint32_t tb = tb0 + st * STG_B;
            const int k0 = c * 64;
#pragma unroll
            for (int j = 0; j < 32; j++) {          // 1024 cp16 per tile / 32 lanes
                const int idx = lane + j * 32;
                const int row = idx >> 3;            // 0..127
                const int seg = idx & 7;             // 16B seg in 128B row
                const uint32_t off = (uint32_t)((row << 7) | (seg << 4));
                cp16(tb + SWZ(off), src + (long long)row * ld + k0 + seg * 8);
            }
            CPASYNC_MBAR_ARRIVE_NOINC(sb + 16 * st);
            if (st == NSTAGE - 1) pph ^= 1;
        }
    } else {
        // ------------------- consumer: 2x2 warps, 64x64 tiles --------------
        const int wm = warp & 1;
        const int wn = warp >> 1;
        const int lr = lane & 15;
        const int lc = lane >> 4;

        float acc[4][8][4];
#pragma unroll
        for (int mt = 0; mt < 4; mt++)
#pragma unroll
            for (int nt = 0; nt < 8; nt++)
#pragma unroll
                for (int e = 0; e < 4; e++)
                    acc[mt][nt][e] = 0.0f;

        int cph = 0;
#pragma unroll 1
        for (int c = 0; c < NC; c++) {
            const int st = (c % NSTAGE);
            MBARRIER_WAIT_PARITY(sb + 16 * st, cph);
            const uint32_t ab = sb + CTRL_B + st * STG_B;
            const uint32_t bb = ab + TILE_B;
#pragma unroll
            for (int ks = 0; ks < 4; ks++) {
                const uint32_t kb = (uint32_t)(ks * 32 + lc * 16);
                uint32_t af[4][4];
                uint32_t bf[4][4];
#pragma unroll
                for (int mt = 0; mt < 4; mt++) {
                    const uint32_t off = (uint32_t)((wm * 64 + mt * 16 + lr) << 7) + kb;
                    LDSM4(af[mt], ab + SWZ(off));
                }
#pragma unroll
                for (int g = 0; g < 4; g++) {
                    const uint32_t off = (uint32_t)((wn * 64 + g * 16 + lr) << 7) + kb;
                    LDSM4(bf[g], bb + SWZ(off));
                }
#pragma unroll
                for (int mt = 0; mt < 4; mt++)
#pragma unroll
                    for (int g = 0; g < 4; g++) {
                        MMA16816(acc[mt][2 * g],     af[mt][0], af[mt][1], af[mt][2], af[mt][3],
                                 bf[g][0], bf[g][2]);
                        MMA16816(acc[mt][2 * g + 1], af[mt][0], af[mt][1], af[mt][2], af[mt][3],
                                 bf[g][1], bf[g][3]);
                    }
            }
            __syncwarp();
            if (elect_one())
                MBARRIER_ARRIVE(sb + 16 * st + 8);
            if (st == NSTAGE - 1) cph ^= 1;
        }

        // Epilogue
        const int tr = lane >> 2;
        const int tc = (lane & 3) * 2;
        const int mbase = m0 + wm * 64;
        const int nbase = n0 + wn * 64;
        if (MODE == 0) {
            // fp16 exp(acc/513 + 1) -> g_wh
            __half* Dh = g_wh + (long long)bz * SEQ * SEQ;
            const float s = 1.0f / 513.0f;
#pragma unroll
            for (int mt = 0; mt < 4; mt++)
#pragma unroll
                for (int nt = 0; nt < 8; nt++) {
                    const float e0 = __expf(acc[mt][nt][0] * s + 1.0f);
                    const float e1 = __expf(acc[mt][nt][1] * s + 1.0f);
                    const float e2 = __expf(acc[mt][nt][2] * s + 1.0f);
                    const float e3 = __expf(acc[mt][nt][3] * s + 1.0f);
                    const int row = mbase + mt * 16 + tr;
                    const int col = nbase + nt * 8 + tc;
                    *(__half2*)(Dh + (long long)row * SEQ + col)       = __floats2half2_rn(e0, e1);
                    *(__half2*)(Dh + (long long)(row + 8) * SEQ + col) = __floats2half2_rn(e2, e3);
                }
        } else {
            float* D = Dbase + (long long)bz * DBS;
#pragma unroll
            for (int mt = 0; mt < 4; mt++)
#pragma unroll
                for (int nt = 0; nt < 8; nt++) {
                    const int row = mbase + mt * 16 + tr;
                    const int col = nbase + nt * 8 + tc;
                    *(float2*)(D + (long long)row * LDD + col) =
                        make_float2(acc[mt][nt][0], acc[mt][nt][1]);
                    *(float2*)(D + (long long)(row + 8) * LDD + col) =
                        make_float2(acc[mt][nt][2], acc[mt][nt][3]);
                }
        }
    }
}

// ===========================================================================
// Kernel 4: normalize — reads fp16 exp from g_wh, writes fp32 weights to W
// and normalized fp16 back to g_wh. (No max needed: scores in [0,2].)
// ===========================================================================
__global__ void normalize_kernel(float* __restrict__ W)
{
    __shared__ float ssum[8];
    const size_t row = blockIdx.x;
    float*  p  = W    + row * SEQ;
    __half* ph = g_wh + row * SEQ;
    const int t = threadIdx.x;

    float v[8];
    float s = 0.0f;
#pragma unroll
    for (int i = 0; i < 8; i++) {
        v[i] = __half2float(ph[t + 256 * i]);
        s += v[i];
    }
#pragma unroll
    for (int o = 16; o; o >>= 1) s += __shfl_xor_sync(0xffffffffu, s, o);
    if ((t & 31) == 0) ssum[t >> 5] = s;
    __syncthreads();
    s = ssum[0];
#pragma unroll
    for (int i = 1; i < 8; i++) s += ssum[i];
    const float inv = 1.0f / s;

#pragma unroll
    for (int i = 0; i < 8; i++) {
        const float w = v[i] * inv;
        p[t + 256 * i]  = w;
        ph[t + 256 * i] = __float2half(w);
    }
}

// ===========================================================================
// Launch: out = [output (B*S*H fp32) | weights (B*S*S fp32)]
// ===========================================================================
extern "C" void kernel_launch(void* const* d_in, const int* in_sizes, int n_in,
                              void* d_out, int out_size)
{
    const float* Q = (const float*)d_in[0];
    const float* K = (const float*)d_in[1];
    const float* V = (const float*)d_in[2];
    float* out     = (float*)d_out;
    float* weights = out + (size_t)BATCH * SEQ * HID;

    cudaFuncSetAttribute(gemm_hmma<0>, cudaFuncAttributeMaxDynamicSharedMemorySize, GEMM_SMEM);
    cudaFuncSetAttribute(gemm_hmma<1>, cudaFuncAttributeMaxDynamicSharedMemorySize, GEMM_SMEM);

    // 0) twiddle table (once per launch; tiny)
    twiddle_init_kernel<<<3, 256>>>();

    // 1) phase features for Q and K (two rows per block)
    fft_phase_kernel<<<ROWS, 256>>>(Q, K);

    // 2) V -> fp16 transposed [b][h][j]
    {
        dim3 grid(HID / 32, SEQ / 32, BATCH);
        vtrans_kernel<<<grid, dim3(32, 8)>>>(V);
    }

    // 3) g_wh = fp16 exp(QF.KF^T/513 + 1)
    {
        dim3 grid(SEQ / 128, SEQ / 128, BATCH);
        gemm_hmma<0><<<grid, 192, GEMM_SMEM>>>(weights);
    }

    // 4) normalize: weights (fp32) + normalized fp16 into g_wh
    normalize_kernel<<<ROWS, 256>>>(weights);

    // 5) output = weights @ V
    {
        dim3 grid(SEQ / 128, HID / 128, BATCH);
        gemm_hmma<1><<<grid, 192, GEMM_SMEM>>>(out);
    }
}